// round 2
// baseline (speedup 1.0000x reference)
#include <cuda_runtime.h>
#include <cuda_bf16.h>

#define BATCH   2
#define CCH     64
#define NTOK    110592      // 48*48*48
#define HEADS   4
#define DHEAD   32
#define KROWS   128         // HEADS*DHEAD
#define NCH     144         // chunks per batch
#define CHUNK   768         // columns per chunk (144*768 = 110592)
#define SUB     128         // columns per smem subtile
#define XSTR    68          // padded stride for x subtile (floats, 16B-aligned rows)

typedef unsigned long long ull;

__device__ __forceinline__ ull ffma2(ull a, ull b, ull c) {
    ull d;
    asm("fma.rn.f32x2 %0, %1, %2, %3;" : "=l"(d) : "l"(a), "l"(b), "l"(c));
    return d;
}
__device__ __forceinline__ ull pack2(float lo, float hi) {
    ull r;
    asm("mov.b64 %0, {%1, %2};" : "=l"(r) : "f"(lo), "f"(hi));
    return r;
}
__device__ __forceinline__ void unpack2(ull v, float& lo, float& hi) {
    asm("mov.b64 {%0, %1}, %2;" : "=f"(lo), "=f"(hi) : "l"(v));
}

// Scratch (no allocations allowed in kernel_launch)
__device__ float g_G_part[BATCH * NCH * KROWS * CCH];  // [b][j][d][c]
__device__ float g_s_part[BATCH * NCH * KROWS];        // [b][j][d]
__device__ float g_G[BATCH * KROWS * CCH];             // [b][d][c]
__device__ float g_s[BATCH * KROWS];                   // [b][d]
__device__ float g_M[BATCH * CCH * CCH];               // [b][c1][c2]

// ---------------------------------------------------------------------------
// Kernel 1: stream x, per column compute k = Wk*x (thread tid owns k-row tid),
// p = exp(k), accumulate G[d,c] += p_d * x_c and s_d += p_d.
// All MACs via packed fma.rn.f32x2.
// ---------------------------------------------------------------------------
__global__ void __launch_bounds__(128, 2)
kv_ctx_kernel(const float* __restrict__ x, const float* __restrict__ wqkv)
{
    const int blk = blockIdx.x;
    const int b   = blk / NCH;
    const int j   = blk - b * NCH;
    const int tid = threadIdx.x;      // k-row index d_global (0..127)

    __shared__ __align__(16) float xs[SUB * XSTR];   // x subtile, [col][c]

    // K weight row (row 128 + tid of wqkv) as 32 f32x2 pairs
    ull wk2[32];
    {
        const ull* kr = reinterpret_cast<const ull*>(wqkv + (size_t)(128 + tid) * 64);
#pragma unroll
        for (int i = 0; i < 32; ++i) wk2[i] = kr[i];
    }

    ull G2[32];
#pragma unroll
    for (int i = 0; i < 32; ++i) G2[i] = 0ull;
    float ssum = 0.f;

    const float* xb = x + (size_t)b * CCH * NTOK + (size_t)j * CHUNK;

    for (int st = 0; st < CHUNK / SUB; ++st) {
        __syncthreads();  // guard previous subtile reads
        const float* xsub = xb + st * SUB;
#pragma unroll 4
        for (int c = 0; c < CCH; ++c)
            xs[tid * XSTR + c] = xsub[(size_t)c * NTOK + tid];
        __syncthreads();

        for (int jb = 0; jb < SUB; jb += 4) {
            const float* xrow = xs + jb * XSTR;
            // --- k phase: 4 columns, packed dot products ---
            ull kk2[4] = {0ull, 0ull, 0ull, 0ull};
#pragma unroll
            for (int c4 = 0; c4 < 16; ++c4) {
#pragma unroll
                for (int jj = 0; jj < 4; ++jj) {
                    ulonglong2 xv = *reinterpret_cast<const ulonglong2*>(xrow + jj * XSTR + c4 * 4);
                    kk2[jj] = ffma2(wk2[2 * c4 + 0], xv.x, kk2[jj]);
                    kk2[jj] = ffma2(wk2[2 * c4 + 1], xv.y, kk2[jj]);
                }
            }
            ull pp2[4];
#pragma unroll
            for (int jj = 0; jj < 4; ++jj) {
                float a, bhi;
                unpack2(kk2[jj], a, bhi);
                float p = __expf(a + bhi);   // |k| ~ O(6): no max subtraction needed
                ssum += p;
                pp2[jj] = pack2(p, p);
            }
            // --- G phase: rank-4 update, packed ---
#pragma unroll
            for (int c4 = 0; c4 < 16; ++c4) {
#pragma unroll
                for (int jj = 0; jj < 4; ++jj) {
                    ulonglong2 xv = *reinterpret_cast<const ulonglong2*>(xrow + jj * XSTR + c4 * 4);
                    G2[2 * c4 + 0] = ffma2(pp2[jj], xv.x, G2[2 * c4 + 0]);
                    G2[2 * c4 + 1] = ffma2(pp2[jj], xv.y, G2[2 * c4 + 1]);
                }
            }
        }
    }

    // Write chunk partials: G row (64 floats) + s
    {
        float* dst = g_G_part + ((size_t)(b * NCH + j) * KROWS + tid) * CCH;
#pragma unroll
        for (int i = 0; i < 16; ++i) {
            ulonglong2 v;
            v.x = G2[2 * i + 0];
            v.y = G2[2 * i + 1];
            *reinterpret_cast<ulonglong2*>(dst + 4 * i) = v;
        }
        g_s_part[(size_t)(b * NCH + j) * KROWS + tid] = ssum;
    }
}

// ---------------------------------------------------------------------------
// Kernel 2a: reduce chunk partials across j (wide: 64 blocks)
// ---------------------------------------------------------------------------
__global__ void __launch_bounds__(256)
reduce_G_kernel()
{
    const int b   = blockIdx.x >> 5;
    const int seg = blockIdx.x & 31;
    const int tid = threadIdx.x;
    const int idx = seg * 256 + tid;            // (d*64 + c) in [0, 8192)

    const float* p = g_G_part + (size_t)b * NCH * (KROWS * CCH) + idx;
    float acc = 0.f;
#pragma unroll 8
    for (int jj = 0; jj < NCH; ++jj) acc += p[(size_t)jj * (KROWS * CCH)];
    g_G[(size_t)b * (KROWS * CCH) + idx] = acc;

    if (seg == 0 && tid < KROWS) {
        const float* q = g_s_part + (size_t)b * NCH * KROWS + tid;
        float a2 = 0.f;
#pragma unroll 8
        for (int jj = 0; jj < NCH; ++jj) a2 += q[jj * KROWS];
        g_s[b * KROWS + tid] = a2;
    }
}

// ---------------------------------------------------------------------------
// Kernel 2b: ctxn[d][e] = (sum_c Wv[h*32+e,c] * G[d,c]) / s[d]
//            T[h*32+e][c] = sum_d ctxn[h*32+d][e] * Wq[h*32+d,c]
//            M[c1][c2]    = sum_o Wout[c1,o] * T[o][c2]
// One block per batch.
// ---------------------------------------------------------------------------
__global__ void __launch_bounds__(256)
proj_kernel(const float* __restrict__ wqkv, const float* __restrict__ wout)
{
    const int b   = blockIdx.x;
    const int tid = threadIdx.x;
    __shared__ float ctxn[KROWS * DHEAD];  // 4096 floats
    __shared__ float Ts[KROWS * CCH];      // 8192 floats

    const float* Gb = g_G + (size_t)b * (KROWS * CCH);
    const float* sb = g_s + b * KROWS;

    for (int idx = tid; idx < KROWS * DHEAD; idx += 256) {
        const int d = idx >> 5;        // global k-row
        const int e = idx & 31;
        const int h = d >> 5;
        const float* wv = wqkv + (size_t)(256 + h * 32 + e) * 64;
        const float* gr = Gb + (size_t)d * CCH;
        float acc = 0.f;
#pragma unroll 8
        for (int c = 0; c < CCH; ++c) acc = fmaf(wv[c], gr[c], acc);
        ctxn[idx] = acc / sb[d];
    }
    __syncthreads();

    for (int idx = tid; idx < KROWS * CCH; idx += 256) {
        const int o = idx >> 6, c = idx & 63;
        const int h = o >> 5, e = o & 31;
        float acc = 0.f;
#pragma unroll 8
        for (int dd = 0; dd < 32; ++dd)
            acc = fmaf(ctxn[((h * 32 + dd) << 5) + e], wqkv[(size_t)(h * 32 + dd) * 64 + c], acc);
        Ts[idx] = acc;
    }
    __syncthreads();

    for (int idx = tid; idx < CCH * CCH; idx += 256) {
        const int c1 = idx >> 6, c2 = idx & 63;
        float acc = 0.f;
#pragma unroll 8
        for (int o = 0; o < KROWS; ++o)
            acc = fmaf(wout[(size_t)c1 * KROWS + o], Ts[o * CCH + c2], acc);
        g_M[(size_t)b * (CCH * CCH) + idx] = acc;
    }
}

// ---------------------------------------------------------------------------
// Kernel 3: out[b][c][n] = sum_c' M[b][c][c'] * x[b][c'][n] + b_out[c]
// Persistent grid-stride over 864 column-tiles of 256; packed FFMA2,
// 4 independent accumulator chains; both batch M matrices cached in smem.
// ---------------------------------------------------------------------------
#define K3_TILES_PB 432                 // 432*256 = 110592
__global__ void __launch_bounds__(256, 2)
out_proj_kernel(const float* __restrict__ x, const float* __restrict__ bout,
                float* __restrict__ out)
{
    const int tid = threadIdx.x;
    __shared__ __align__(16) float Ms[BATCH][CCH * CCH];  // 32KB
    __shared__ float bo[CCH];
    for (int i = tid; i < BATCH * CCH * CCH; i += 256)
        Ms[i >> 12][i & 4095] = g_M[i];
    if (tid < CCH) bo[tid] = bout[tid];
    __syncthreads();

    for (int t = blockIdx.x; t < BATCH * K3_TILES_PB; t += gridDim.x) {
        const int b = (t >= K3_TILES_PB) ? 1 : 0;
        const int n = (t - b * K3_TILES_PB) * 256 + tid;
        const float* xb = x   + (size_t)b * CCH * NTOK;
        float*       ob = out + (size_t)b * CCH * NTOK;

        ull xc2[32];
#pragma unroll
        for (int c2 = 0; c2 < 32; ++c2) {
            float a  = xb[(size_t)(2 * c2 + 0) * NTOK + n];
            float bh = xb[(size_t)(2 * c2 + 1) * NTOK + n];
            xc2[c2] = pack2(a, bh);
        }
        const float* M = Ms[b];

        for (int co = 0; co < CCH; co += 4) {
            ull acc[4] = {0ull, 0ull, 0ull, 0ull};
#pragma unroll
            for (int c4 = 0; c4 < 16; ++c4) {
#pragma unroll
                for (int r = 0; r < 4; ++r) {
                    ulonglong2 m = *reinterpret_cast<const ulonglong2*>(M + (co + r) * 64 + c4 * 4);
                    acc[r] = ffma2(m.x, xc2[2 * c4 + 0], acc[r]);
                    acc[r] = ffma2(m.y, xc2[2 * c4 + 1], acc[r]);
                }
            }
#pragma unroll
            for (int r = 0; r < 4; ++r) {
                float lo, hi;
                unpack2(acc[r], lo, hi);
                ob[(size_t)(co + r) * NTOK + n] = bo[co + r] + lo + hi;
            }
        }
    }
}

extern "C" void kernel_launch(void* const* d_in, const int* in_sizes, int n_in,
                              void* d_out, int out_size)
{
    const float* x    = (const float*)d_in[0];
    const float* wqkv = (const float*)d_in[1];
    const float* wout = (const float*)d_in[2];
    const float* bout = (const float*)d_in[3];
    float* out = (float*)d_out;

    kv_ctx_kernel<<<BATCH * NCH, 128>>>(x, wqkv);
    reduce_G_kernel<<<BATCH * 32, 256>>>();
    proj_kernel<<<BATCH, 256>>>(wqkv, wout);
    out_proj_kernel<<<296, 256>>>(x, bout, out);
}

// round 3
// speedup vs baseline: 1.2972x; 1.2972x over previous
#include <cuda_runtime.h>
#include <cuda_bf16.h>
#include <cstdint>

#define BATCH   2
#define CCH     64
#define NTOK    110592      // 48*48*48
#define KROWS   128         // HEADS*DHEAD
#define TN      128         // n-tile width
#define NSUB    864         // NTOK / TN
#define NPB     74          // blocks per batch (grid 148)
#define XS      136         // X smem row stride (floats/words)
#define PS      132         // P smem row stride (floats)

// smem byte offsets (K1)
#define RAW_BYTES   (64 * XS * 4)            // 34816 per buffer
#define OFF_XSH     (2 * RAW_BYTES)          // 69632
#define OFF_XSL     (OFF_XSH + RAW_BYTES)    // 104448
#define OFF_PS      (OFF_XSL + RAW_BYTES)    // 139264
#define SMEM_K1     (OFF_PS + 128 * PS * 4)  // 206848
#define SMEM_K3     (OFF_XSL + RAW_BYTES)    // 139264

typedef uint32_t u32;

// ---------------- PTX helpers ----------------
__device__ __forceinline__ u32 f2tf32(float x) {
    u32 r; asm("cvt.rna.tf32.f32 %0, %1;" : "=r"(r) : "f"(x)); return r;
}
__device__ __forceinline__ void mma8(float& d0, float& d1, float& d2, float& d3,
                                     u32 a0, u32 a1, u32 a2, u32 a3, u32 b0, u32 b1) {
    asm volatile("mma.sync.aligned.m16n8k8.row.col.f32.tf32.tf32.f32 "
                 "{%0,%1,%2,%3}, {%4,%5,%6,%7}, {%8,%9}, {%0,%1,%2,%3};"
                 : "+f"(d0), "+f"(d1), "+f"(d2), "+f"(d3)
                 : "r"(a0), "r"(a1), "r"(a2), "r"(a3), "r"(b0), "r"(b1));
}
__device__ __forceinline__ void cpasync16(u32 dst, const void* src) {
    asm volatile("cp.async.cg.shared.global [%0], [%1], 16;" :: "r"(dst), "l"(src));
}
__device__ __forceinline__ void cp_commit() { asm volatile("cp.async.commit_group;"); }
__device__ __forceinline__ void cp_wait0()  { asm volatile("cp.async.wait_group 0;"); }
__device__ __forceinline__ void cp_wait1()  { asm volatile("cp.async.wait_group 1;"); }

// Scratch
__device__ float g_G_part[BATCH * NPB * KROWS * CCH];
__device__ float g_s_part[BATCH * NPB * KROWS];
__device__ float g_G[BATCH * KROWS * CCH];
__device__ float g_s[BATCH * KROWS];
__device__ float g_M[BATCH * CCH * CCH];

// issue cp.async for one 64x128 f32 tile into smem buffer at byte offset
__device__ __forceinline__ void tile_issue(u32 sbase, const float* gsrc, int tid) {
#pragma unroll
    for (int rep = 0; rep < 8; ++rep) {
        int idx = rep * 256 + tid;
        int row = idx >> 5;
        int c16 = idx & 31;
        cpasync16(sbase + (u32)(row * XS + c16 * 4) * 4,
                  gsrc + (size_t)row * NTOK + c16 * 4);
    }
}

// split raw f32 tile -> tf32 hi/lo u32 tiles (same [64][XS] layout)
__device__ __forceinline__ void tile_split(const float* raw, u32* xh, u32* xl, int tid) {
#pragma unroll
    for (int i = 0; i < 9; ++i) {
        int idx4 = i * 256 + tid;
        if (idx4 < (64 * XS) / 4) {
            float4 v = *reinterpret_cast<const float4*>(raw + idx4 * 4);
            u32 h0 = f2tf32(v.x), h1 = f2tf32(v.y), h2 = f2tf32(v.z), h3 = f2tf32(v.w);
            u32 l0 = f2tf32(v.x - __uint_as_float(h0));
            u32 l1 = f2tf32(v.y - __uint_as_float(h1));
            u32 l2 = f2tf32(v.z - __uint_as_float(h2));
            u32 l3 = f2tf32(v.w - __uint_as_float(h3));
            *reinterpret_cast<uint4*>(xh + idx4 * 4) = make_uint4(h0, h1, h2, h3);
            *reinterpret_cast<uint4*>(xl + idx4 * 4) = make_uint4(l0, l1, l2, l3);
        }
    }
}

// ---------------------------------------------------------------------------
// Kernel 1 (tensor): per tile, k = Wk*X (GEMM1, tf32 3x), p = exp(k) via smem,
// G += P*X^T (GEMM2, tf32 3x). Per-block G/s partials.
// ---------------------------------------------------------------------------
__global__ void __launch_bounds__(256, 1)
kv_ctx_kernel(const float* __restrict__ x, const float* __restrict__ wqkv)
{
    extern __shared__ __align__(16) unsigned char smem[];
    float* raw  = reinterpret_cast<float*>(smem);              // [2][64*XS]
    u32*   xsh  = reinterpret_cast<u32*>(smem + OFF_XSH);
    u32*   xsl  = reinterpret_cast<u32*>(smem + OFF_XSL);
    float* Pst  = reinterpret_cast<float*>(smem + OFF_PS);     // [128][PS]
    u32 sbase;
    asm("{ .reg .u64 t; cvta.to.shared.u64 t, %1; cvt.u32.u64 %0, t; }"
        : "=r"(sbase) : "l"(smem));

    const int tid  = threadIdx.x;
    const int wrp  = tid >> 5;
    const int lane = tid & 31;
    const int gid  = lane >> 2;
    const int tig  = lane & 3;

    const int b    = blockIdx.x / NPB;
    const int part = blockIdx.x - b * NPB;
    const int s0   = (part * NSUB) / NPB;
    const int s1   = ((part + 1) * NSUB) / NPB;

    // W_k A-fragments (rows 128..255 of wqkv), split hi/lo
    u32 wah[8][4], wal[8][4];
    {
        const float* wb = wqkv + (size_t)(128 + 16 * wrp) * 64;
#pragma unroll
        for (int kb = 0; kb < 8; ++kb) {
            float v0 = wb[(size_t)gid       * 64 + kb * 8 + tig];
            float v1 = wb[(size_t)(gid + 8) * 64 + kb * 8 + tig];
            float v2 = wb[(size_t)gid       * 64 + kb * 8 + tig + 4];
            float v3 = wb[(size_t)(gid + 8) * 64 + kb * 8 + tig + 4];
            wah[kb][0] = f2tf32(v0); wal[kb][0] = f2tf32(v0 - __uint_as_float(wah[kb][0]));
            wah[kb][1] = f2tf32(v1); wal[kb][1] = f2tf32(v1 - __uint_as_float(wah[kb][1]));
            wah[kb][2] = f2tf32(v2); wal[kb][2] = f2tf32(v2 - __uint_as_float(wah[kb][2]));
            wah[kb][3] = f2tf32(v3); wal[kb][3] = f2tf32(v3 - __uint_as_float(wah[kb][3]));
        }
    }

    float ga[8][4];
#pragma unroll
    for (int c = 0; c < 8; ++c) { ga[c][0] = ga[c][1] = ga[c][2] = ga[c][3] = 0.f; }
    float srow0 = 0.f, srow1 = 0.f;

    const float* xb = x + (size_t)b * CCH * NTOK;
    const int prow0 = (16 * wrp + gid) * PS;
    const int prow1 = prow0 + 8 * PS;

    tile_issue(sbase, xb + (size_t)s0 * TN, tid);
    cp_commit();

    for (int s = s0; s < s1; ++s) {
        const int cur = (s - s0) & 1;
        __syncthreads();                       // prev compute done (buf cur^1 free)
        if (s + 1 < s1) {
            tile_issue(sbase + (cur ^ 1) * RAW_BYTES, xb + (size_t)(s + 1) * TN, tid);
            cp_commit();
            cp_wait1();
        } else {
            cp_wait0();
        }
        __syncthreads();
        tile_split(raw + cur * (64 * XS), xsh, xsl, tid);
        __syncthreads();

        // ---- GEMM1: C[16 nb][4] = Wk * Xtile ----
        float C[16][4];
#pragma unroll
        for (int nb = 0; nb < 16; ++nb) { C[nb][0] = C[nb][1] = C[nb][2] = C[nb][3] = 0.f; }
#pragma unroll
        for (int kb = 0; kb < 8; ++kb) {
            const int r0 = (kb * 8 + tig) * XS;
            const int r1 = r0 + 4 * XS;
#pragma unroll
            for (int nbp = 0; nbp < 8; ++nbp) {
                const int nb0 = 2 * nbp, nb1 = nb0 + 1;
                const int c0 = nb0 * 8 + gid, c1 = nb1 * 8 + gid;
                u32 b0h = xsh[r0 + c0], b1h = xsh[r1 + c0];
                u32 b0l = xsl[r0 + c0], b1l = xsl[r1 + c0];
                u32 d0h = xsh[r0 + c1], d1h = xsh[r1 + c1];
                u32 d0l = xsl[r0 + c1], d1l = xsl[r1 + c1];
                mma8(C[nb0][0], C[nb0][1], C[nb0][2], C[nb0][3],
                     wah[kb][0], wah[kb][1], wah[kb][2], wah[kb][3], b0h, b1h);
                mma8(C[nb1][0], C[nb1][1], C[nb1][2], C[nb1][3],
                     wah[kb][0], wah[kb][1], wah[kb][2], wah[kb][3], d0h, d1h);
                mma8(C[nb0][0], C[nb0][1], C[nb0][2], C[nb0][3],
                     wah[kb][0], wah[kb][1], wah[kb][2], wah[kb][3], b0l, b1l);
                mma8(C[nb1][0], C[nb1][1], C[nb1][2], C[nb1][3],
                     wah[kb][0], wah[kb][1], wah[kb][2], wah[kb][3], d0l, d1l);
                mma8(C[nb0][0], C[nb0][1], C[nb0][2], C[nb0][3],
                     wal[kb][0], wal[kb][1], wal[kb][2], wal[kb][3], b0h, b1h);
                mma8(C[nb1][0], C[nb1][1], C[nb1][2], C[nb1][3],
                     wal[kb][0], wal[kb][1], wal[kb][2], wal[kb][3], d0h, d1h);
            }
        }

        // ---- exp + row sums + stage P ----
#pragma unroll
        for (int nb = 0; nb < 16; ++nb) {
            float p0 = __expf(C[nb][0]);
            float p1 = __expf(C[nb][1]);
            float p2 = __expf(C[nb][2]);
            float p3 = __expf(C[nb][3]);
            srow0 += p0 + p1;
            srow1 += p2 + p3;
            *reinterpret_cast<float2*>(Pst + prow0 + nb * 8 + 2 * tig) = make_float2(p0, p1);
            *reinterpret_cast<float2*>(Pst + prow1 + nb * 8 + 2 * tig) = make_float2(p2, p3);
        }
        __syncwarp();

        // ---- GEMM2: G[16 rows][64 c] += P * X^T ----
#pragma unroll
        for (int kb = 0; kb < 16; ++kb) {
            float a0f = Pst[prow0 + kb * 8 + tig];
            float a1f = Pst[prow1 + kb * 8 + tig];
            float a2f = Pst[prow0 + kb * 8 + tig + 4];
            float a3f = Pst[prow1 + kb * 8 + tig + 4];
            u32 ah0 = f2tf32(a0f), ah1 = f2tf32(a1f), ah2 = f2tf32(a2f), ah3 = f2tf32(a3f);
            u32 al0 = f2tf32(a0f - __uint_as_float(ah0));
            u32 al1 = f2tf32(a1f - __uint_as_float(ah1));
            u32 al2 = f2tf32(a2f - __uint_as_float(ah2));
            u32 al3 = f2tf32(a3f - __uint_as_float(ah3));
            const int kc = kb * 8 + tig;
#pragma unroll
            for (int cbp = 0; cbp < 4; ++cbp) {
                const int cb0 = 2 * cbp, cb1 = cb0 + 1;
                u32 b0h = xsh[(cb0 * 8 + gid) * XS + kc];
                u32 b1h = xsh[(cb0 * 8 + gid) * XS + kc + 4];
                u32 b0l = xsl[(cb0 * 8 + gid) * XS + kc];
                u32 b1l = xsl[(cb0 * 8 + gid) * XS + kc + 4];
                u32 e0h = xsh[(cb1 * 8 + gid) * XS + kc];
                u32 e1h = xsh[(cb1 * 8 + gid) * XS + kc + 4];
                u32 e0l = xsl[(cb1 * 8 + gid) * XS + kc];
                u32 e1l = xsl[(cb1 * 8 + gid) * XS + kc + 4];
                mma8(ga[cb0][0], ga[cb0][1], ga[cb0][2], ga[cb0][3],
                     ah0, ah1, ah2, ah3, b0h, b1h);
                mma8(ga[cb1][0], ga[cb1][1], ga[cb1][2], ga[cb1][3],
                     ah0, ah1, ah2, ah3, e0h, e1h);
                mma8(ga[cb0][0], ga[cb0][1], ga[cb0][2], ga[cb0][3],
                     ah0, ah1, ah2, ah3, b0l, b1l);
                mma8(ga[cb1][0], ga[cb1][1], ga[cb1][2], ga[cb1][3],
                     ah0, ah1, ah2, ah3, e0l, e1l);
                mma8(ga[cb0][0], ga[cb0][1], ga[cb0][2], ga[cb0][3],
                     al0, al1, al2, al3, b0h, b1h);
                mma8(ga[cb1][0], ga[cb1][1], ga[cb1][2], ga[cb1][3],
                     al0, al1, al2, al3, e0h, e1h);
            }
        }
    }

    // ---- write partials ----
    {
        float* gp = g_G_part + (size_t)(b * NPB + part) * KROWS * CCH;
        const int r0 = 16 * wrp + gid, r1 = r0 + 8;
#pragma unroll
        for (int cb = 0; cb < 8; ++cb) {
            *reinterpret_cast<float2*>(gp + (size_t)r0 * CCH + cb * 8 + 2 * tig) =
                make_float2(ga[cb][0], ga[cb][1]);
            *reinterpret_cast<float2*>(gp + (size_t)r1 * CCH + cb * 8 + 2 * tig) =
                make_float2(ga[cb][2], ga[cb][3]);
        }
        srow0 += __shfl_xor_sync(0xffffffffu, srow0, 1);
        srow0 += __shfl_xor_sync(0xffffffffu, srow0, 2);
        srow1 += __shfl_xor_sync(0xffffffffu, srow1, 1);
        srow1 += __shfl_xor_sync(0xffffffffu, srow1, 2);
        if (tig == 0) {
            float* sp = g_s_part + (size_t)(b * NPB + part) * KROWS;
            sp[r0] = srow0;
            sp[r1] = srow1;
        }
    }
}

// ---------------------------------------------------------------------------
// Kernel 2a: reduce partials over NPB
// ---------------------------------------------------------------------------
__global__ void __launch_bounds__(256)
reduce_G_kernel()
{
    const int b   = blockIdx.x >> 5;
    const int idx = (blockIdx.x & 31) * 256 + threadIdx.x;   // [0, 8192)
    const float* p = g_G_part + (size_t)b * NPB * (KROWS * CCH) + idx;
    float acc = 0.f;
#pragma unroll 8
    for (int j = 0; j < NPB; ++j) acc += p[(size_t)j * (KROWS * CCH)];
    g_G[(size_t)b * (KROWS * CCH) + idx] = acc;

    if ((blockIdx.x & 31) == 0 && threadIdx.x < KROWS) {
        const float* q = g_s_part + (size_t)b * NPB * KROWS + threadIdx.x;
        float a2 = 0.f;
#pragma unroll 8
        for (int j = 0; j < NPB; ++j) a2 += q[j * KROWS];
        g_s[b * KROWS + threadIdx.x] = a2;
    }
}

// ---------------------------------------------------------------------------
// Kernel 2b: ctx -> T -> M  (tiny, one block per batch)
// ---------------------------------------------------------------------------
__global__ void __launch_bounds__(256)
proj_kernel(const float* __restrict__ wqkv, const float* __restrict__ wout)
{
    const int b   = blockIdx.x;
    const int tid = threadIdx.x;
    __shared__ float ctxn[KROWS * 32];
    __shared__ float Ts[KROWS * CCH];

    const float* Gb = g_G + (size_t)b * (KROWS * CCH);
    const float* sb = g_s + b * KROWS;

    for (int idx = tid; idx < KROWS * 32; idx += 256) {
        const int d = idx >> 5, e = idx & 31, h = d >> 5;
        const float* wv = wqkv + (size_t)(256 + h * 32 + e) * 64;
        const float* gr = Gb + (size_t)d * CCH;
        float acc = 0.f;
#pragma unroll 8
        for (int c = 0; c < CCH; ++c) acc = fmaf(wv[c], gr[c], acc);
        ctxn[idx] = acc / sb[d];
    }
    __syncthreads();

    for (int idx = tid; idx < KROWS * CCH; idx += 256) {
        const int o = idx >> 6, c = idx & 63;
        const int h = o >> 5, e = o & 31;
        float acc = 0.f;
#pragma unroll 8
        for (int dd = 0; dd < 32; ++dd)
            acc = fmaf(ctxn[((h * 32 + dd) << 5) + e], wqkv[(size_t)(h * 32 + dd) * 64 + c], acc);
        Ts[idx] = acc;
    }
    __syncthreads();

    for (int idx = tid; idx < CCH * CCH; idx += 256) {
        const int c1 = idx >> 6, c2 = idx & 63;
        float acc = 0.f;
#pragma unroll 8
        for (int o = 0; o < KROWS; ++o)
            acc = fmaf(wout[(size_t)c1 * KROWS + o], Ts[o * CCH + c2], acc);
        g_M[(size_t)b * (CCH * CCH) + idx] = acc;
    }
}

// ---------------------------------------------------------------------------
// Kernel 3 (tensor): out = M * X + b_out.  8 warps = 4 m-strips x 2 n-halves.
// ---------------------------------------------------------------------------
__global__ void __launch_bounds__(256, 1)
out_proj_kernel(const float* __restrict__ x, const float* __restrict__ bout,
                float* __restrict__ out)
{
    extern __shared__ __align__(16) unsigned char smem[];
    float* raw = reinterpret_cast<float*>(smem);
    u32*   xsh = reinterpret_cast<u32*>(smem + OFF_XSH);
    u32*   xsl = reinterpret_cast<u32*>(smem + OFF_XSL);
    u32 sbase;
    asm("{ .reg .u64 t; cvta.to.shared.u64 t, %1; cvt.u32.u64 %0, t; }"
        : "=r"(sbase) : "l"(smem));

    const int tid  = threadIdx.x;
    const int wrp  = tid >> 5;
    const int lane = tid & 31;
    const int gid  = lane >> 2;
    const int tig  = lane & 3;
    const int ms   = wrp & 3;     // m-strip (rows 16*ms..)
    const int nh   = wrp >> 2;    // n-half (0..1)

    const int b    = blockIdx.x / NPB;
    const int part = blockIdx.x - b * NPB;
    const int s0   = (part * NSUB) / NPB;
    const int s1   = ((part + 1) * NSUB) / NPB;

    // M A-fragments, split
    u32 mah[8][4], mal[8][4];
    {
        const float* Mb = g_M + (size_t)b * (CCH * CCH) + (size_t)(16 * ms) * 64;
#pragma unroll
        for (int kb = 0; kb < 8; ++kb) {
            float v0 = Mb[(size_t)gid       * 64 + kb * 8 + tig];
            float v1 = Mb[(size_t)(gid + 8) * 64 + kb * 8 + tig];
            float v2 = Mb[(size_t)gid       * 64 + kb * 8 + tig + 4];
            float v3 = Mb[(size_t)(gid + 8) * 64 + kb * 8 + tig + 4];
            mah[kb][0] = f2tf32(v0); mal[kb][0] = f2tf32(v0 - __uint_as_float(mah[kb][0]));
            mah[kb][1] = f2tf32(v1); mal[kb][1] = f2tf32(v1 - __uint_as_float(mah[kb][1]));
            mah[kb][2] = f2tf32(v2); mal[kb][2] = f2tf32(v2 - __uint_as_float(mah[kb][2]));
            mah[kb][3] = f2tf32(v3); mal[kb][3] = f2tf32(v3 - __uint_as_float(mah[kb][3]));
        }
    }
    const float bias0 = bout[16 * ms + gid];
    const float bias1 = bout[16 * ms + gid + 8];

    const float* xb = x   + (size_t)b * CCH * NTOK;
    float*       ob = out + (size_t)b * CCH * NTOK;

    tile_issue(sbase, xb + (size_t)s0 * TN, tid);
    cp_commit();

    for (int s = s0; s < s1; ++s) {
        const int cur = (s - s0) & 1;
        __syncthreads();
        if (s + 1 < s1) {
            tile_issue(sbase + (cur ^ 1) * RAW_BYTES, xb + (size_t)(s + 1) * TN, tid);
            cp_commit();
            cp_wait1();
        } else {
            cp_wait0();
        }
        __syncthreads();
        tile_split(raw + cur * (64 * XS), xsh, xsl, tid);
        __syncthreads();

        float C[8][4];
#pragma unroll
        for (int nb = 0; nb < 8; ++nb) { C[nb][0] = C[nb][1] = C[nb][2] = C[nb][3] = 0.f; }
#pragma unroll
        for (int kb = 0; kb < 8; ++kb) {
            const int r0 = (kb * 8 + tig) * XS;
            const int r1 = r0 + 4 * XS;
#pragma unroll
            for (int nbp = 0; nbp < 4; ++nbp) {
                const int nb0 = 2 * nbp, nb1 = nb0 + 1;
                const int c0 = nh * 64 + nb0 * 8 + gid;
                const int c1 = c0 + 8;
                u32 b0h = xsh[r0 + c0], b1h = xsh[r1 + c0];
                u32 b0l = xsl[r0 + c0], b1l = xsl[r1 + c0];
                u32 e0h = xsh[r0 + c1], e1h = xsh[r1 + c1];
                u32 e0l = xsl[r0 + c1], e1l = xsl[r1 + c1];
                mma8(C[nb0][0], C[nb0][1], C[nb0][2], C[nb0][3],
                     mah[kb][0], mah[kb][1], mah[kb][2], mah[kb][3], b0h, b1h);
                mma8(C[nb1][0], C[nb1][1], C[nb1][2], C[nb1][3],
                     mah[kb][0], mah[kb][1], mah[kb][2], mah[kb][3], e0h, e1h);
                mma8(C[nb0][0], C[nb0][1], C[nb0][2], C[nb0][3],
                     mah[kb][0], mah[kb][1], mah[kb][2], mah[kb][3], b0l, b1l);
                mma8(C[nb1][0], C[nb1][1], C[nb1][2], C[nb1][3],
                     mah[kb][0], mah[kb][1], mah[kb][2], mah[kb][3], e0l, e1l);
                mma8(C[nb0][0], C[nb0][1], C[nb0][2], C[nb0][3],
                     mal[kb][0], mal[kb][1], mal[kb][2], mal[kb][3], b0h, b1h);
                mma8(C[nb1][0], C[nb1][1], C[nb1][2], C[nb1][3],
                     mal[kb][0], mal[kb][1], mal[kb][2], mal[kb][3], e0h, e1h);
            }
        }

        const int r0 = 16 * ms + gid, r1 = r0 + 8;
        const int nbase = s * TN + nh * 64 + 2 * tig;
#pragma unroll
        for (int nb = 0; nb < 8; ++nb) {
            const int n = nbase + nb * 8;
            *reinterpret_cast<float2*>(ob + (size_t)r0 * NTOK + n) =
                make_float2(C[nb][0] + bias0, C[nb][1] + bias0);
            *reinterpret_cast<float2*>(ob + (size_t)r1 * NTOK + n) =
                make_float2(C[nb][2] + bias1, C[nb][3] + bias1);
        }
    }
}

extern "C" void kernel_launch(void* const* d_in, const int* in_sizes, int n_in,
                              void* d_out, int out_size)
{
    const float* x    = (const float*)d_in[0];
    const float* wqkv = (const float*)d_in[1];
    const float* wout = (const float*)d_in[2];
    const float* bout = (const float*)d_in[3];
    float* out = (float*)d_out;

    cudaFuncSetAttribute(kv_ctx_kernel,   cudaFuncAttributeMaxDynamicSharedMemorySize, SMEM_K1);
    cudaFuncSetAttribute(out_proj_kernel, cudaFuncAttributeMaxDynamicSharedMemorySize, SMEM_K3);

    kv_ctx_kernel<<<BATCH * NPB, 256, SMEM_K1>>>(x, wqkv);
    reduce_G_kernel<<<BATCH * 32, 256>>>();
    proj_kernel<<<BATCH, 256>>>(wqkv, wout);
    out_proj_kernel<<<BATCH * NPB, 256, SMEM_K3>>>(x, bout, out);
}

// round 4
// speedup vs baseline: 1.5115x; 1.1652x over previous
#include <cuda_runtime.h>
#include <cuda_bf16.h>
#include <cstdint>

#define BATCH   2
#define CCH     64
#define NTOK    110592      // 48*48*48
#define KROWS   128
#define TN      64          // tile width (n columns)
#define TILES   1728        // NTOK / TN, per batch
#define NPB     74          // parts per batch -> grid 148
#define SW      36          // smem row stride in u32 words (72 bf16)

typedef uint32_t u32;

// ---------------- helpers ----------------
__device__ __forceinline__ float bhi(float v) {
    return __bfloat162float(__float2bfloat16_rn(v));
}
__device__ __forceinline__ u32 pk(float lo, float hi) {
    __nv_bfloat162 p = __floats2bfloat162_rn(lo, hi);   // .x = lo half
    return reinterpret_cast<u32&>(p);
}
// split pair (a=lower index, b=next) into hi-plane and lo-plane packed regs
__device__ __forceinline__ void sp2(float a, float b, u32& h, u32& l) {
    float ha = bhi(a), hb = bhi(b);
    h = pk(ha, hb);
    l = pk(a - ha, b - hb);
}
__device__ __forceinline__ void mma16(float (&d)[4], const u32 (&a)[4], u32 b0, u32 b1) {
    asm volatile("mma.sync.aligned.m16n8k16.row.col.f32.bf16.bf16.f32 "
                 "{%0,%1,%2,%3}, {%4,%5,%6,%7}, {%8,%9}, {%0,%1,%2,%3};"
                 : "+f"(d[0]), "+f"(d[1]), "+f"(d[2]), "+f"(d[3])
                 : "r"(a[0]), "r"(a[1]), "r"(a[2]), "r"(a[3]), "r"(b0), "r"(b1));
}

// Scratch
__device__ float g_G_part[BATCH * NPB * KROWS * CCH];
__device__ float g_s_part[BATCH * NPB * KROWS];
__device__ float g_G[BATCH * KROWS * CCH];
__device__ float g_s[BATCH * KROWS];
__device__ float g_M[BATCH * CCH * CCH];

// ---------------------------------------------------------------------------
// Kernel 1: per 64-col tile: k = Wk*X (bf16x3 mma), p = exp(k),
// G += P*X^T (bf16x3 mma). 512 threads = 16 warps: warp = (ms 0..7) x (nh 0..1).
// smem planes: X1[n][c] (GEMM1 B), X2[c][n] (GEMM2 B), P[d][n] (GEMM2 A).
// ---------------------------------------------------------------------------
__global__ void __launch_bounds__(512, 1)
kv_ctx_kernel(const float* __restrict__ x, const float* __restrict__ wqkv)
{
    extern __shared__ __align__(16) u32 sm[];
    u32* X1h = sm;                 // 64*SW
    u32* X1l = sm + 2304;
    u32* X2h = sm + 4608;
    u32* X2l = sm + 6912;
    u32* Ph  = sm + 9216;          // 128*SW
    u32* Pl  = sm + 13824;
    float* sred = reinterpret_cast<float*>(sm + 18432);  // 256 floats

    const int tid  = threadIdx.x;
    const int wrp  = tid >> 5;
    const int lane = tid & 31;
    const int g    = lane >> 2;
    const int t    = lane & 3;
    const int ms   = wrp & 7;      // 16-row d-strip
    const int nh   = wrp >> 3;     // half (n for GEMM1, c for GEMM2)

    const int b    = blockIdx.x / NPB;
    const int part = blockIdx.x - b * NPB;
    const int s0   = (part * TILES) / NPB;
    const int s1   = ((part + 1) * TILES) / NPB;

    // ---- Wk fragments (rows 128 + 16*ms .. +16), bf16 hi/lo ----
    u32 wh[4][4], wl[4][4];
    {
        const float* w0 = wqkv + (size_t)(128 + 16 * ms + g) * 64;
        const float* w1 = w0 + (size_t)8 * 64;
#pragma unroll
        for (int kc = 0; kc < 4; ++kc) {
            sp2(w0[16*kc + 2*t],     w0[16*kc + 2*t + 1], wh[kc][0], wl[kc][0]);
            sp2(w1[16*kc + 2*t],     w1[16*kc + 2*t + 1], wh[kc][1], wl[kc][1]);
            sp2(w0[16*kc + 2*t + 8], w0[16*kc + 2*t + 9], wh[kc][2], wl[kc][2]);
            sp2(w1[16*kc + 2*t + 8], w1[16*kc + 2*t + 9], wh[kc][3], wl[kc][3]);
        }
    }

    float ga[4][4];
#pragma unroll
    for (int cb = 0; cb < 4; ++cb) { ga[cb][0]=ga[cb][1]=ga[cb][2]=ga[cb][3]=0.f; }
    float srow0 = 0.f, srow1 = 0.f;

    // loader: thread owns 4 c-rows x 2 n-cols
    const int lc = 4 * (tid >> 5);       // c base (0..60)
    const int ln = 2 * (tid & 31);       // n base within tile (0..62)
    const float* xg = x + (size_t)b * CCH * NTOK + (size_t)lc * NTOK + ln;
    float2 cur[4], nxt[4];
#pragma unroll
    for (int r = 0; r < 4; ++r)
        cur[r] = *reinterpret_cast<const float2*>(xg + (size_t)r * NTOK + (size_t)s0 * TN);

    const int prow0 = (16 * ms + g) * SW;
    const int prow1 = prow0 + 8 * SW;

    for (int s = s0; s < s1; ++s) {
        __syncthreads();   // previous tile fully consumed
        if (s + 1 < s1) {
#pragma unroll
            for (int r = 0; r < 4; ++r)
                nxt[r] = *reinterpret_cast<const float2*>(xg + (size_t)r * NTOK + (size_t)(s + 1) * TN);
        }
        // ---- stage current tile into bf16 hi/lo planes ----
        {
            float h0[4], h1[4], l0[4], l1[4];
#pragma unroll
            for (int r = 0; r < 4; ++r) {
                h0[r] = bhi(cur[r].x); l0[r] = cur[r].x - h0[r];
                h1[r] = bhi(cur[r].y); l1[r] = cur[r].y - h1[r];
            }
#pragma unroll
            for (int r = 0; r < 4; ++r) {   // X2[c][n]
                X2h[(lc + r) * SW + (ln >> 1)] = pk(h0[r], h1[r]);
                X2l[(lc + r) * SW + (ln >> 1)] = pk(l0[r], l1[r]);
            }
            // X1[n][c]
            *reinterpret_cast<uint2*>(&X1h[ln * SW + (lc >> 1)]) =
                make_uint2(pk(h0[0], h0[1]), pk(h0[2], h0[3]));
            *reinterpret_cast<uint2*>(&X1l[ln * SW + (lc >> 1)]) =
                make_uint2(pk(l0[0], l0[1]), pk(l0[2], l0[3]));
            *reinterpret_cast<uint2*>(&X1h[(ln + 1) * SW + (lc >> 1)]) =
                make_uint2(pk(h1[0], h1[1]), pk(h1[2], h1[3]));
            *reinterpret_cast<uint2*>(&X1l[(ln + 1) * SW + (lc >> 1)]) =
                make_uint2(pk(l1[0], l1[1]), pk(l1[2], l1[3]));
        }
        __syncthreads();

        // ---- GEMM1: C = Wk * X  (warp: 16 d-rows x 32 n) ----
        float C[4][4];
#pragma unroll
        for (int nb = 0; nb < 4; ++nb) { C[nb][0]=C[nb][1]=C[nb][2]=C[nb][3]=0.f; }
#pragma unroll
        for (int kc = 0; kc < 4; ++kc) {
#pragma unroll
            for (int nb = 0; nb < 4; ++nb) {
                const int row = (nh * 32 + nb * 8 + g) * SW + 8 * kc + t;
                u32 b0h = X1h[row], b1h = X1h[row + 4];
                u32 b0l = X1l[row], b1l = X1l[row + 4];
                mma16(C[nb], wh[kc], b0h, b1h);
                mma16(C[nb], wh[kc], b0l, b1l);
                mma16(C[nb], wl[kc], b0h, b1h);
            }
        }

        // ---- exp + row-sums + stage P hi/lo ----
#pragma unroll
        for (int nb = 0; nb < 4; ++nb) {
            float p0 = __expf(C[nb][0]);
            float p1 = __expf(C[nb][1]);
            float p2 = __expf(C[nb][2]);
            float p3 = __expf(C[nb][3]);
            srow0 += p0 + p1;
            srow1 += p2 + p3;
            const int w = 16 * nh + 4 * nb + t;
            u32 hA, lA, hB, lB;
            sp2(p0, p1, hA, lA);
            sp2(p2, p3, hB, lB);
            Ph[prow0 + w] = hA;  Pl[prow0 + w] = lA;
            Ph[prow1 + w] = hB;  Pl[prow1 + w] = lB;
        }
        __syncthreads();   // P complete across both n-halves

        // ---- GEMM2: G += P * X^T  (warp: 16 d-rows x 32 c) ----
#pragma unroll
        for (int kn = 0; kn < 4; ++kn) {
            u32 Ah[4], Al[4];
            Ah[0] = Ph[prow0 + 8*kn + t];     Al[0] = Pl[prow0 + 8*kn + t];
            Ah[1] = Ph[prow1 + 8*kn + t];     Al[1] = Pl[prow1 + 8*kn + t];
            Ah[2] = Ph[prow0 + 8*kn + t + 4]; Al[2] = Pl[prow0 + 8*kn + t + 4];
            Ah[3] = Ph[prow1 + 8*kn + t + 4]; Al[3] = Pl[prow1 + 8*kn + t + 4];
#pragma unroll
            for (int cb = 0; cb < 4; ++cb) {
                const int xr = (nh * 32 + cb * 8 + g) * SW + 8 * kn + t;
                u32 b0h = X2h[xr], b1h = X2h[xr + 4];
                u32 b0l = X2l[xr], b1l = X2l[xr + 4];
                mma16(ga[cb], Ah, b0h, b1h);
                mma16(ga[cb], Ah, b0l, b1l);
                mma16(ga[cb], Al, b0h, b1h);
            }
        }
#pragma unroll
        for (int r = 0; r < 4; ++r) cur[r] = nxt[r];
    }

    // ---- write partials ----
    {
        float* gp = g_G_part + (size_t)(b * NPB + part) * KROWS * CCH;
        const int r0 = 16 * ms + g, r1 = r0 + 8;
#pragma unroll
        for (int cb = 0; cb < 4; ++cb) {
            const int col = nh * 32 + cb * 8 + 2 * t;
            *reinterpret_cast<float2*>(gp + (size_t)r0 * CCH + col) = make_float2(ga[cb][0], ga[cb][1]);
            *reinterpret_cast<float2*>(gp + (size_t)r1 * CCH + col) = make_float2(ga[cb][2], ga[cb][3]);
        }
        srow0 += __shfl_xor_sync(0xffffffffu, srow0, 1);
        srow0 += __shfl_xor_sync(0xffffffffu, srow0, 2);
        srow1 += __shfl_xor_sync(0xffffffffu, srow1, 1);
        srow1 += __shfl_xor_sync(0xffffffffu, srow1, 2);
        if (t == 0) {
            sred[nh * 128 + 16 * ms + g]     = srow0;
            sred[nh * 128 + 16 * ms + g + 8] = srow1;
        }
        __syncthreads();
        if (tid < KROWS)
            g_s_part[(size_t)(b * NPB + part) * KROWS + tid] = sred[tid] + sred[128 + tid];
    }
}

// ---------------------------------------------------------------------------
// Kernel 2a: reduce partials over NPB parts
// ---------------------------------------------------------------------------
__global__ void __launch_bounds__(256)
reduce_G_kernel()
{
    const int b   = blockIdx.x >> 5;
    const int idx = (blockIdx.x & 31) * 256 + threadIdx.x;   // [0, 8192)
    const float* p = g_G_part + (size_t)b * NPB * (KROWS * CCH) + idx;
    float acc = 0.f;
#pragma unroll 8
    for (int j = 0; j < NPB; ++j) acc += p[(size_t)j * (KROWS * CCH)];
    g_G[(size_t)b * (KROWS * CCH) + idx] = acc;

    if ((blockIdx.x & 31) == 0 && threadIdx.x < KROWS) {
        const float* q = g_s_part + (size_t)b * NPB * KROWS + threadIdx.x;
        float a2 = 0.f;
#pragma unroll 8
        for (int j = 0; j < NPB; ++j) a2 += q[j * KROWS];
        g_s[b * KROWS + threadIdx.x] = a2;
    }
}

// ---------------------------------------------------------------------------
// Kernel 2b: ctx -> T -> M  (tiny, one block per batch)
// ---------------------------------------------------------------------------
__global__ void __launch_bounds__(256)
proj_kernel(const float* __restrict__ wqkv, const float* __restrict__ wout)
{
    const int b   = blockIdx.x;
    const int tid = threadIdx.x;
    __shared__ float ctxn[KROWS * 32];
    __shared__ float Ts[KROWS * CCH];

    const float* Gb = g_G + (size_t)b * (KROWS * CCH);
    const float* sb = g_s + b * KROWS;

    for (int idx = tid; idx < KROWS * 32; idx += 256) {
        const int d = idx >> 5, e = idx & 31, h = d >> 5;
        const float* wv = wqkv + (size_t)(256 + h * 32 + e) * 64;
        const float* gr = Gb + (size_t)d * CCH;
        float acc = 0.f;
#pragma unroll 8
        for (int c = 0; c < CCH; ++c) acc = fmaf(wv[c], gr[c], acc);
        ctxn[idx] = acc / sb[d];
    }
    __syncthreads();

    for (int idx = tid; idx < KROWS * CCH; idx += 256) {
        const int o = idx >> 6, c = idx & 63;
        const int h = o >> 5, e = o & 31;
        float acc = 0.f;
#pragma unroll 8
        for (int dd = 0; dd < 32; ++dd)
            acc = fmaf(ctxn[((h * 32 + dd) << 5) + e], wqkv[(size_t)(h * 32 + dd) * 64 + c], acc);
        Ts[idx] = acc;
    }
    __syncthreads();

    for (int idx = tid; idx < CCH * CCH; idx += 256) {
        const int c1 = idx >> 6, c2 = idx & 63;
        float acc = 0.f;
#pragma unroll 8
        for (int o = 0; o < KROWS; ++o)
            acc = fmaf(wout[(size_t)c1 * KROWS + o], Ts[o * CCH + c2], acc);
        g_M[(size_t)b * (CCH * CCH) + idx] = acc;
    }
}

// ---------------------------------------------------------------------------
// Kernel 3: out = M*X + b_out (bf16x3 mma). 512 thr: warp = (ms 0..3) x (nh 0..3)
// ---------------------------------------------------------------------------
__global__ void __launch_bounds__(512, 1)
out_proj_kernel(const float* __restrict__ x, const float* __restrict__ bout,
                float* __restrict__ out)
{
    __shared__ __align__(16) u32 X1h[64 * SW];
    __shared__ __align__(16) u32 X1l[64 * SW];

    const int tid  = threadIdx.x;
    const int wrp  = tid >> 5;
    const int lane = tid & 31;
    const int g    = lane >> 2;
    const int t    = lane & 3;
    const int ms   = wrp & 3;      // 16-row out-channel strip
    const int nh   = wrp >> 2;     // 16-col n quarter

    const int b    = blockIdx.x / NPB;
    const int part = blockIdx.x - b * NPB;
    const int s0   = (part * TILES) / NPB;
    const int s1   = ((part + 1) * TILES) / NPB;

    // M fragments
    u32 mh[4][4], ml[4][4];
    {
        const float* M0 = g_M + (size_t)b * (CCH * CCH) + (size_t)(16 * ms + g) * 64;
        const float* M1 = M0 + (size_t)8 * 64;
#pragma unroll
        for (int kc = 0; kc < 4; ++kc) {
            sp2(M0[16*kc + 2*t],     M0[16*kc + 2*t + 1], mh[kc][0], ml[kc][0]);
            sp2(M1[16*kc + 2*t],     M1[16*kc + 2*t + 1], mh[kc][1], ml[kc][1]);
            sp2(M0[16*kc + 2*t + 8], M0[16*kc + 2*t + 9], mh[kc][2], ml[kc][2]);
            sp2(M1[16*kc + 2*t + 8], M1[16*kc + 2*t + 9], mh[kc][3], ml[kc][3]);
        }
    }
    const float bias0 = bout[16 * ms + g];
    const float bias1 = bout[16 * ms + g + 8];

    const int lc = 4 * (tid >> 5);
    const int ln = 2 * (tid & 31);
    const float* xg = x   + (size_t)b * CCH * NTOK + (size_t)lc * NTOK + ln;
    float*       ob = out + (size_t)b * CCH * NTOK;

    float2 cur[4], nxt[4];
#pragma unroll
    for (int r = 0; r < 4; ++r)
        cur[r] = *reinterpret_cast<const float2*>(xg + (size_t)r * NTOK + (size_t)s0 * TN);

    for (int s = s0; s < s1; ++s) {
        __syncthreads();
        if (s + 1 < s1) {
#pragma unroll
            for (int r = 0; r < 4; ++r)
                nxt[r] = *reinterpret_cast<const float2*>(xg + (size_t)r * NTOK + (size_t)(s + 1) * TN);
        }
        {
            float h0[4], h1[4], l0[4], l1[4];
#pragma unroll
            for (int r = 0; r < 4; ++r) {
                h0[r] = bhi(cur[r].x); l0[r] = cur[r].x - h0[r];
                h1[r] = bhi(cur[r].y); l1[r] = cur[r].y - h1[r];
            }
            *reinterpret_cast<uint2*>(&X1h[ln * SW + (lc >> 1)]) =
                make_uint2(pk(h0[0], h0[1]), pk(h0[2], h0[3]));
            *reinterpret_cast<uint2*>(&X1l[ln * SW + (lc >> 1)]) =
                make_uint2(pk(l0[0], l0[1]), pk(l0[2], l0[3]));
            *reinterpret_cast<uint2*>(&X1h[(ln + 1) * SW + (lc >> 1)]) =
                make_uint2(pk(h1[0], h1[1]), pk(h1[2], h1[3]));
            *reinterpret_cast<uint2*>(&X1l[(ln + 1) * SW + (lc >> 1)]) =
                make_uint2(pk(l1[0], l1[1]), pk(l1[2], l1[3]));
        }
        __syncthreads();

        float C[2][4];
#pragma unroll
        for (int nb = 0; nb < 2; ++nb) { C[nb][0]=C[nb][1]=C[nb][2]=C[nb][3]=0.f; }
#pragma unroll
        for (int kc = 0; kc < 4; ++kc) {
#pragma unroll
            for (int nb = 0; nb < 2; ++nb) {
                const int row = (nh * 16 + nb * 8 + g) * SW + 8 * kc + t;
                u32 b0h = X1h[row], b1h = X1h[row + 4];
                u32 b0l = X1l[row], b1l = X1l[row + 4];
                mma16(C[nb], mh[kc], b0h, b1h);
                mma16(C[nb], mh[kc], b0l, b1l);
                mma16(C[nb], ml[kc], b0h, b1h);
            }
        }

        const int r0 = 16 * ms + g, r1 = r0 + 8;
#pragma unroll
        for (int nb = 0; nb < 2; ++nb) {
            const int n = s * TN + nh * 16 + nb * 8 + 2 * t;
            *reinterpret_cast<float2*>(ob + (size_t)r0 * NTOK + n) =
                make_float2(C[nb][0] + bias0, C[nb][1] + bias0);
            *reinterpret_cast<float2*>(ob + (size_t)r1 * NTOK + n) =
                make_float2(C[nb][2] + bias1, C[nb][3] + bias1);
        }
#pragma unroll
        for (int r = 0; r < 4; ++r) cur[r] = nxt[r];
    }
}

extern "C" void kernel_launch(void* const* d_in, const int* in_sizes, int n_in,
                              void* d_out, int out_size)
{
    const float* x    = (const float*)d_in[0];
    const float* wqkv = (const float*)d_in[1];
    const float* wout = (const float*)d_in[2];
    const float* bout = (const float*)d_in[3];
    float* out = (float*)d_out;

    const int smem_k1 = 18432 * 4 + 256 * 4;   // 74752 B
    cudaFuncSetAttribute(kv_ctx_kernel, cudaFuncAttributeMaxDynamicSharedMemorySize, smem_k1);

    kv_ctx_kernel<<<BATCH * NPB, 512, smem_k1>>>(x, wqkv);
    reduce_G_kernel<<<BATCH * 32, 256>>>();
    proj_kernel<<<BATCH, 256>>>(wqkv, wout);
    out_proj_kernel<<<BATCH * NPB, 512>>>(x, bout, out);
}

// round 6
// speedup vs baseline: 1.6131x; 1.0672x over previous
#include <cuda_runtime.h>
#include <cuda_bf16.h>
#include <cstdint>

#define BATCH   2
#define CCH     64
#define NTOK    110592      // 48*48*48
#define KROWS   128
#define TN      128         // tile width (n columns)
#define TILES   864         // NTOK / TN per batch
#define NPB     74          // parts per batch -> grid 148
#define RAWS    132         // raw f32 row stride (floats)
#define SW2     68          // X2 row stride in u32 words (136 bf16)
#define RAWW    8448        // 64*RAWS (u32 words per raw buffer)
#define X2OFF   16896       // word offset of X2h
#define PLANEB  17408       // bytes between X2h and X2l (4352 words)
#define SREDOFF 25600       // word offset of sred (K1)

typedef uint32_t u32;

// ---------------- helpers ----------------
__device__ __forceinline__ float bhi(float v) {
    return __bfloat162float(__float2bfloat16_rn(v));
}
__device__ __forceinline__ u32 pk(float lo, float hi) {
    __nv_bfloat162 p = __floats2bfloat162_rn(lo, hi);   // .x = lo half
    return reinterpret_cast<u32&>(p);
}
__device__ __forceinline__ void sp2(float a, float b, u32& h, u32& l) {
    float ha = bhi(a), hb = bhi(b);
    h = pk(ha, hb);
    l = pk(a - ha, b - hb);
}
// lo-plane from already-packed hi reg (exact: bf16 bits<<16 == value)
__device__ __forceinline__ u32 losplit(u32 h, float a, float b) {
    float ha = __uint_as_float(h << 16);
    float hb = __uint_as_float(h & 0xffff0000u);
    return pk(a - ha, b - hb);
}
__device__ __forceinline__ void mma16(float (&d)[4], const u32 (&a)[4], u32 b0, u32 b1) {
    asm volatile("mma.sync.aligned.m16n8k16.row.col.f32.bf16.bf16.f32 "
                 "{%0,%1,%2,%3}, {%4,%5,%6,%7}, {%8,%9}, {%0,%1,%2,%3};"
                 : "+f"(d[0]), "+f"(d[1]), "+f"(d[2]), "+f"(d[3])
                 : "r"(a[0]), "r"(a[1]), "r"(a[2]), "r"(a[3]), "r"(b0), "r"(b1));
}
__device__ __forceinline__ void ldsm4t(u32& r0, u32& r1, u32& r2, u32& r3, u32 addr) {
    asm volatile("ldmatrix.sync.aligned.m8n8.x4.trans.shared.b16 {%0,%1,%2,%3}, [%4];"
                 : "=r"(r0), "=r"(r1), "=r"(r2), "=r"(r3) : "r"(addr));
}
__device__ __forceinline__ void ldsm4(u32& r0, u32& r1, u32& r2, u32& r3, u32 addr) {
    asm volatile("ldmatrix.sync.aligned.m8n8.x4.shared.b16 {%0,%1,%2,%3}, [%4];"
                 : "=r"(r0), "=r"(r1), "=r"(r2), "=r"(r3) : "r"(addr));
}
__device__ __forceinline__ void cpasync16(u32 dst, const void* src) {
    asm volatile("cp.async.cg.shared.global [%0], [%1], 16;" :: "r"(dst), "l"(src));
}
__device__ __forceinline__ void cp_commit() { asm volatile("cp.async.commit_group;"); }
__device__ __forceinline__ void cp_wait0()  { asm volatile("cp.async.wait_group 0;"); }
__device__ __forceinline__ void cp_wait1()  { asm volatile("cp.async.wait_group 1;"); }

// Scratch
__device__ float g_G_part[BATCH * NPB * KROWS * CCH];
__device__ float g_s_part[BATCH * NPB * KROWS];
__device__ float g_G[BATCH * KROWS * CCH];
__device__ float g_s[BATCH * KROWS];
__device__ float g_M[BATCH * CCH * CCH];

// cp.async one 64x128 f32 tile into raw buffer (word offset off)
__device__ __forceinline__ void tile_issue(u32 sbase, u32 off, const float* xb,
                                           int s, int tid) {
#pragma unroll
    for (int i = 0; i < 4; ++i) {
        int idx = i * 512 + tid;
        int row = idx >> 5, c16 = idx & 31;
        cpasync16(sbase + (off + (u32)(row * RAWS + c16 * 4)) * 4,
                  xb + (size_t)row * NTOK + (size_t)s * TN + c16 * 4);
    }
}

// stage raw f32 -> X2 hi/lo bf16 planes ([c][n], stride SW2)
__device__ __forceinline__ void tile_stage(const u32* sm, u32* X2h, u32* X2l,
                                           int cur, int wrp, int lane) {
    const float* rp = reinterpret_cast<const float*>(sm) + cur * RAWW;
    const int lc = 4 * wrp;
#pragma unroll
    for (int r = 0; r < 4; ++r) {
        float4 v = *reinterpret_cast<const float4*>(rp + (lc + r) * RAWS + 4 * lane);
        u32 h0 = pk(bhi(v.x), bhi(v.y));
        u32 h1 = pk(bhi(v.z), bhi(v.w));
        u32 l0 = losplit(h0, v.x, v.y);
        u32 l1 = losplit(h1, v.z, v.w);
        *reinterpret_cast<uint2*>(&X2h[(lc + r) * SW2 + 2 * lane]) = make_uint2(h0, h1);
        *reinterpret_cast<uint2*>(&X2l[(lc + r) * SW2 + 2 * lane]) = make_uint2(l0, l1);
    }
}

// ---------------------------------------------------------------------------
// Kernel 1: per 128-col tile: k = Wk*X (bf16x3), p = exp(k) in registers,
// G += P*X^T (bf16x3, P re-used as A-fragments directly).
// 16 warps: (ms 0..7 d-strip) x (nh 0..1 n-half). G halves combined via smem.
// ---------------------------------------------------------------------------
__global__ void __launch_bounds__(512, 1)
kv_ctx_kernel(const float* __restrict__ x, const float* __restrict__ wqkv)
{
    extern __shared__ __align__(16) u32 sm[];
    u32* X2h = sm + X2OFF;
    u32* X2l = sm + X2OFF + 4352;
    float* sred = reinterpret_cast<float*>(sm + SREDOFF);
    u32 sbase;
    asm("{ .reg .u64 t; cvta.to.shared.u64 t, %1; cvt.u32.u64 %0, t; }"
        : "=r"(sbase) : "l"(sm));

    const int tid  = threadIdx.x;
    const int wrp  = tid >> 5;
    const int lane = tid & 31;
    const int g    = lane >> 2;
    const int t    = lane & 3;
    const int ms   = wrp & 7;
    const int nh   = wrp >> 3;

    const int b    = blockIdx.x / NPB;
    const int part = blockIdx.x - b * NPB;
    const int s0   = (part * TILES) / NPB;
    const int s1   = ((part + 1) * TILES) / NPB;

    // Wk fragments (rows 128 + 16*ms .. +16), bf16 hi/lo
    u32 wh[4][4], wl[4][4];
    {
        const float* w0 = wqkv + (size_t)(128 + 16 * ms + g) * 64;
        const float* w1 = w0 + (size_t)8 * 64;
#pragma unroll
        for (int kc = 0; kc < 4; ++kc) {
            sp2(w0[16*kc + 2*t],     w0[16*kc + 2*t + 1], wh[kc][0], wl[kc][0]);
            sp2(w1[16*kc + 2*t],     w1[16*kc + 2*t + 1], wh[kc][1], wl[kc][1]);
            sp2(w0[16*kc + 2*t + 8], w0[16*kc + 2*t + 9], wh[kc][2], wl[kc][2]);
            sp2(w1[16*kc + 2*t + 8], w1[16*kc + 2*t + 9], wh[kc][3], wl[kc][3]);
        }
    }

    float ga[8][4];
#pragma unroll
    for (int cb = 0; cb < 8; ++cb) { ga[cb][0]=ga[cb][1]=ga[cb][2]=ga[cb][3]=0.f; }
    float srow0 = 0.f, srow1 = 0.f;

    // ldmatrix base byte-offsets (lane-dependent)
    const u32 X2hB = sbase + X2OFF * 4;
    const int r1l = lane & 15;                          // GEMM1 (trans): rows = c
    const int w1o = (lane >> 4) << 2;                   // n-word select
    const u32 a1base = X2hB + (u32)((r1l * SW2 + nh * 32 + w1o) * 4);
    const int r2l = ((lane >> 4) & 1) * 8 + (lane & 7); // GEMM2: rows = c
    const int w2o = ((lane >> 3) & 1) * 4;
    const u32 a2base = X2hB + (u32)((r2l * SW2 + nh * 32 + w2o) * 4);

    const float* xb = x + (size_t)b * CCH * NTOK;

    tile_issue(sbase, 0, xb, s0, tid);
    cp_commit();

    for (int s = s0; s < s1; ++s) {
        const int cur = (s - s0) & 1;
        if (s + 1 < s1) {
            tile_issue(sbase, (cur ^ 1) * RAWW, xb, s + 1, tid);
            cp_commit();
            cp_wait1();
        } else {
            cp_wait0();
        }
        __syncthreads();          // raw[cur] ready AND prev compute done
        tile_stage(sm, X2h, X2l, cur, wrp, lane);
        __syncthreads();

#pragma unroll
        for (int p = 0; p < 4; ++p) {
            // ---- GEMM1: C pair (16 d x 16 n) ----
            float C0[4] = {0.f,0.f,0.f,0.f}, C1[4] = {0.f,0.f,0.f,0.f};
#pragma unroll
            for (int kc = 0; kc < 4; ++kc) {
                const u32 ah = a1base + (u32)(kc * (16 * SW2 * 4) + p * 32);
                u32 h0,h1,h2,h3, l0,l1,l2,l3;
                ldsm4t(h0, h1, h2, h3, ah);
                ldsm4t(l0, l1, l2, l3, ah + PLANEB);
                mma16(C0, wh[kc], h0, h1);
                mma16(C0, wh[kc], l0, l1);
                mma16(C0, wl[kc], h0, h1);
                mma16(C1, wh[kc], h2, h3);
                mma16(C1, wh[kc], l2, l3);
                mma16(C1, wl[kc], h2, h3);
            }
            // ---- exp in registers -> P fragments ----
            float e00 = __expf(C0[0]), e01 = __expf(C0[1]);
            float e02 = __expf(C0[2]), e03 = __expf(C0[3]);
            float e10 = __expf(C1[0]), e11 = __expf(C1[1]);
            float e12 = __expf(C1[2]), e13 = __expf(C1[3]);
            srow0 += e00 + e01 + e10 + e11;
            srow1 += e02 + e03 + e12 + e13;
            u32 Ah[4], Al[4];
            Ah[0] = pk(bhi(e00), bhi(e01)); Al[0] = losplit(Ah[0], e00, e01);
            Ah[1] = pk(bhi(e02), bhi(e03)); Al[1] = losplit(Ah[1], e02, e03);
            Ah[2] = pk(bhi(e10), bhi(e11)); Al[2] = losplit(Ah[2], e10, e11);
            Ah[3] = pk(bhi(e12), bhi(e13)); Al[3] = losplit(Ah[3], e12, e13);
            // ---- GEMM2: G += P * X^T over this 16-n k-block ----
#pragma unroll
            for (int pp = 0; pp < 4; ++pp) {
                const u32 a2 = a2base + (u32)(pp * (16 * SW2 * 4) + p * 32);
                u32 h0,h1,h2,h3, l0,l1,l2,l3;
                ldsm4(h0, h1, h2, h3, a2);
                ldsm4(l0, l1, l2, l3, a2 + PLANEB);
                mma16(ga[2*pp],   Ah, h0, h1);
                mma16(ga[2*pp],   Ah, l0, l1);
                mma16(ga[2*pp],   Al, h0, h1);
                mma16(ga[2*pp+1], Ah, h2, h3);
                mma16(ga[2*pp+1], Ah, l2, l3);
                mma16(ga[2*pp+1], Al, h2, h3);
            }
        }
    }

    // ---- s reduce ----
    srow0 += __shfl_xor_sync(0xffffffffu, srow0, 1);
    srow0 += __shfl_xor_sync(0xffffffffu, srow0, 2);
    srow1 += __shfl_xor_sync(0xffffffffu, srow1, 1);
    srow1 += __shfl_xor_sync(0xffffffffu, srow1, 2);
    if (t == 0) {
        sred[nh * 128 + 16 * ms + g]     = srow0;
        sred[nh * 128 + 16 * ms + g + 8] = srow1;
    }
    __syncthreads();

    // ---- combine G halves across nh via smem (reuse raw area) ----
    float* gred = reinterpret_cast<float*>(sm);
    const int r0 = 16 * ms + g, r1 = r0 + 8;
    if (nh == 1) {
#pragma unroll
        for (int cb = 0; cb < 8; ++cb) {
            const int col = cb * 8 + 2 * t;
            *reinterpret_cast<float2*>(&gred[r0 * 64 + col]) = make_float2(ga[cb][0], ga[cb][1]);
            *reinterpret_cast<float2*>(&gred[r1 * 64 + col]) = make_float2(ga[cb][2], ga[cb][3]);
        }
    }
    __syncthreads();
    if (nh == 0) {
        float* gp = g_G_part + (size_t)(b * NPB + part) * (KROWS * CCH);
#pragma unroll
        for (int cb = 0; cb < 8; ++cb) {
            const int col = cb * 8 + 2 * t;
            *reinterpret_cast<float2*>(gp + (size_t)r0 * CCH + col) =
                make_float2(ga[cb][0] + gred[r0 * 64 + col], ga[cb][1] + gred[r0 * 64 + col + 1]);
            *reinterpret_cast<float2*>(gp + (size_t)r1 * CCH + col) =
                make_float2(ga[cb][2] + gred[r1 * 64 + col], ga[cb][3] + gred[r1 * 64 + col + 1]);
        }
    }
    if (tid < KROWS)
        g_s_part[(size_t)(b * NPB + part) * KROWS + tid] = sred[tid] + sred[128 + tid];
}

// ---------------------------------------------------------------------------
// Kernel 2a: reduce partials over NPB parts
// ---------------------------------------------------------------------------
__global__ void __launch_bounds__(256)
reduce_G_kernel()
{
    const int b   = blockIdx.x >> 5;
    const int idx = (blockIdx.x & 31) * 256 + threadIdx.x;
    const float* p = g_G_part + (size_t)b * NPB * (KROWS * CCH) + idx;
    float acc = 0.f;
#pragma unroll 8
    for (int j = 0; j < NPB; ++j) acc += p[(size_t)j * (KROWS * CCH)];
    g_G[(size_t)b * (KROWS * CCH) + idx] = acc;

    if ((blockIdx.x & 31) == 0 && threadIdx.x < KROWS) {
        const float* q = g_s_part + (size_t)b * NPB * KROWS + threadIdx.x;
        float a2 = 0.f;
#pragma unroll 8
        for (int j = 0; j < NPB; ++j) a2 += q[j * KROWS];
        g_s[b * KROWS + threadIdx.x] = a2;
    }
}

// ---------------------------------------------------------------------------
// Kernel 2b: ctx -> T -> M  (tiny, one block per batch)
// ---------------------------------------------------------------------------
__global__ void __launch_bounds__(256)
proj_kernel(const float* __restrict__ wqkv, const float* __restrict__ wout)
{
    const int b   = blockIdx.x;
    const int tid = threadIdx.x;
    __shared__ float ctxn[KROWS * 32];
    __shared__ float Ts[KROWS * CCH];

    const float* Gb = g_G + (size_t)b * (KROWS * CCH);
    const float* sb = g_s + b * KROWS;

    for (int idx = tid; idx < KROWS * 32; idx += 256) {
        const int d = idx >> 5, e = idx & 31, h = d >> 5;
        const float* wv = wqkv + (size_t)(256 + h * 32 + e) * 64;
        const float* gr = Gb + (size_t)d * CCH;
        float acc = 0.f;
#pragma unroll 8
        for (int c = 0; c < CCH; ++c) acc = fmaf(wv[c], gr[c], acc);
        ctxn[idx] = acc / sb[d];
    }
    __syncthreads();

    for (int idx = tid; idx < KROWS * CCH; idx += 256) {
        const int o = idx >> 6, c = idx & 63;
        const int h = o >> 5, e = o & 31;
        float acc = 0.f;
#pragma unroll 8
        for (int dd = 0; dd < 32; ++dd)
            acc = fmaf(ctxn[((h * 32 + dd) << 5) + e], wqkv[(size_t)(h * 32 + dd) * 64 + c], acc);
        Ts[idx] = acc;
    }
    __syncthreads();

    for (int idx = tid; idx < CCH * CCH; idx += 256) {
        const int c1 = idx >> 6, c2 = idx & 63;
        float acc = 0.f;
#pragma unroll 8
        for (int o = 0; o < KROWS; ++o)
            acc = fmaf(wout[(size_t)c1 * KROWS + o], Ts[o * CCH + c2], acc);
        g_M[(size_t)b * (CCH * CCH) + idx] = acc;
    }
}

// ---------------------------------------------------------------------------
// Kernel 3: out = M*X + b_out. 16 warps = (ms 0..3) x (nh 0..3), TN=128,
// cp.async raw + bf16 hi/lo plane, trans-ldmatrix B fragments.
// ---------------------------------------------------------------------------
__global__ void __launch_bounds__(512, 1)
out_proj_kernel(const float* __restrict__ x, const float* __restrict__ bout,
                float* __restrict__ out)
{
    extern __shared__ __align__(16) u32 sm[];
    u32* X2h = sm + X2OFF;
    u32* X2l = sm + X2OFF + 4352;
    u32 sbase;
    asm("{ .reg .u64 t; cvta.to.shared.u64 t, %1; cvt.u32.u64 %0, t; }"
        : "=r"(sbase) : "l"(sm));

    const int tid  = threadIdx.x;
    const int wrp  = tid >> 5;
    const int lane = tid & 31;
    const int g    = lane >> 2;
    const int t    = lane & 3;
    const int ms   = wrp & 3;
    const int nh   = wrp >> 2;

    const int b    = blockIdx.x / NPB;
    const int part = blockIdx.x - b * NPB;
    const int s0   = (part * TILES) / NPB;
    const int s1   = ((part + 1) * TILES) / NPB;

    // M fragments
    u32 mh[4][4], ml[4][4];
    {
        const float* M0 = g_M + (size_t)b * (CCH * CCH) + (size_t)(16 * ms + g) * 64;
        const float* M1 = M0 + (size_t)8 * 64;
#pragma unroll
        for (int kc = 0; kc < 4; ++kc) {
            sp2(M0[16*kc + 2*t],     M0[16*kc + 2*t + 1], mh[kc][0], ml[kc][0]);
            sp2(M1[16*kc + 2*t],     M1[16*kc + 2*t + 1], mh[kc][1], ml[kc][1]);
            sp2(M0[16*kc + 2*t + 8], M0[16*kc + 2*t + 9], mh[kc][2], ml[kc][2]);
            sp2(M1[16*kc + 2*t + 8], M1[16*kc + 2*t + 9], mh[kc][3], ml[kc][3]);
        }
    }
    const float bias0 = bout[16 * ms + g];
    const float bias1 = bout[16 * ms + g + 8];

    const u32 X2hB = sbase + X2OFF * 4;
    const int r1l = lane & 15;
    const int w1o = (lane >> 4) << 2;
    const u32 a1base = X2hB + (u32)((r1l * SW2 + nh * 16 + w1o) * 4);

    const float* xb = x   + (size_t)b * CCH * NTOK;
    float*       ob = out + (size_t)b * CCH * NTOK;

    tile_issue(sbase, 0, xb, s0, tid);
    cp_commit();

    for (int s = s0; s < s1; ++s) {
        const int cur = (s - s0) & 1;
        if (s + 1 < s1) {
            tile_issue(sbase, (cur ^ 1) * RAWW, xb, s + 1, tid);
            cp_commit();
            cp_wait1();
        } else {
            cp_wait0();
        }
        __syncthreads();
        tile_stage(sm, X2h, X2l, cur, wrp, lane);
        __syncthreads();

        float C[4][4];
#pragma unroll
        for (int nb = 0; nb < 4; ++nb) { C[nb][0]=C[nb][1]=C[nb][2]=C[nb][3]=0.f; }
#pragma unroll
        for (int kc = 0; kc < 4; ++kc) {
#pragma unroll
            for (int pp = 0; pp < 2; ++pp) {
                const u32 ah = a1base + (u32)(kc * (16 * SW2 * 4) + pp * 32);
                u32 h0,h1,h2,h3, l0,l1,l2,l3;
                ldsm4t(h0, h1, h2, h3, ah);
                ldsm4t(l0, l1, l2, l3, ah + PLANEB);
                mma16(C[2*pp],   mh[kc], h0, h1);
                mma16(C[2*pp],   mh[kc], l0, l1);
                mma16(C[2*pp],   ml[kc], h0, h1);
                mma16(C[2*pp+1], mh[kc], h2, h3);
                mma16(C[2*pp+1], mh[kc], l2, l3);
                mma16(C[2*pp+1], ml[kc], h2, h3);
            }
        }

        const int r0 = 16 * ms + g, r1 = r0 + 8;
#pragma unroll
        for (int nb = 0; nb < 4; ++nb) {
            const int n = s * TN + nh * 32 + nb * 8 + 2 * t;
            *reinterpret_cast<float2*>(ob + (size_t)r0 * NTOK + n) =
                make_float2(C[nb][0] + bias0, C[nb][1] + bias0);
            *reinterpret_cast<float2*>(ob + (size_t)r1 * NTOK + n) =
                make_float2(C[nb][2] + bias1, C[nb][3] + bias1);
        }
    }
}

extern "C" void kernel_launch(void* const* d_in, const int* in_sizes, int n_in,
                              void* d_out, int out_size)
{
    const float* x    = (const float*)d_in[0];
    const float* wqkv = (const float*)d_in[1];
    const float* wout = (const float*)d_in[2];
    const float* bout = (const float*)d_in[3];
    float* out = (float*)d_out;

    const int smem_k1 = (SREDOFF + 256) * 4;   // 103424 B
    const int smem_k3 = SREDOFF * 4;           // 102400 B
    cudaFuncSetAttribute(kv_ctx_kernel,   cudaFuncAttributeMaxDynamicSharedMemorySize, smem_k1);
    cudaFuncSetAttribute(out_proj_kernel, cudaFuncAttributeMaxDynamicSharedMemorySize, smem_k3);

    kv_ctx_kernel<<<BATCH * NPB, 512, smem_k1>>>(x, wqkv);
    reduce_G_kernel<<<BATCH * 32, 256>>>();
    proj_kernel<<<BATCH, 256>>>(wqkv, wout);
    out_proj_kernel<<<BATCH * NPB, 512, smem_k3>>>(x, bout, out);
}

// round 10
// speedup vs baseline: 1.6135x; 1.0002x over previous
#include <cuda_runtime.h>
#include <cuda_bf16.h>
#include <cstdint>

#define BATCH   2
#define CCH     64
#define NTOK    110592      // 48*48*48
#define KROWS   128
#define TN      128         // tile width (n columns)
#define TILES   864         // NTOK / TN per batch
#define NPB     74          // parts per batch -> grid 148
#define RAWS    132         // raw f32 row stride (floats)
#define SW2     68          // X2 row stride in u32 words (136 bf16)
#define RAWW    8448        // 64*RAWS (u32 words per raw buffer)
#define X2OFF   16896       // word offset of X2h
#define PLANEB  17408       // bytes between X2h and X2l (4352 words)
#define SREDOFF 25600       // word offset of sred (K1)

typedef uint32_t u32;

// ---------------- helpers ----------------
__device__ __forceinline__ float bhi(float v) {
    return __bfloat162float(__float2bfloat16_rn(v));
}
__device__ __forceinline__ u32 pk(float lo, float hi) {
    __nv_bfloat162 p = __floats2bfloat162_rn(lo, hi);   // .x = lo half
    return reinterpret_cast<u32&>(p);
}
__device__ __forceinline__ void sp2(float a, float b, u32& h, u32& l) {
    float ha = bhi(a), hb = bhi(b);
    h = pk(ha, hb);
    l = pk(a - ha, b - hb);
}
// lo-plane from already-packed hi reg (exact: bf16 bits<<16 == value)
__device__ __forceinline__ u32 losplit(u32 h, float a, float b) {
    float ha = __uint_as_float(h << 16);
    float hb = __uint_as_float(h & 0xffff0000u);
    return pk(a - ha, b - hb);
}
__device__ __forceinline__ void mma16(float (&d)[4], const u32 (&a)[4], u32 b0, u32 b1) {
    asm volatile("mma.sync.aligned.m16n8k16.row.col.f32.bf16.bf16.f32 "
                 "{%0,%1,%2,%3}, {%4,%5,%6,%7}, {%8,%9}, {%0,%1,%2,%3};"
                 : "+f"(d[0]), "+f"(d[1]), "+f"(d[2]), "+f"(d[3])
                 : "r"(a[0]), "r"(a[1]), "r"(a[2]), "r"(a[3]), "r"(b0), "r"(b1));
}
__device__ __forceinline__ void ldsm4t(u32& r0, u32& r1, u32& r2, u32& r3, u32 addr) {
    asm volatile("ldmatrix.sync.aligned.m8n8.x4.trans.shared.b16 {%0,%1,%2,%3}, [%4];"
                 : "=r"(r0), "=r"(r1), "=r"(r2), "=r"(r3) : "r"(addr));
}
__device__ __forceinline__ void ldsm4(u32& r0, u32& r1, u32& r2, u32& r3, u32 addr) {
    asm volatile("ldmatrix.sync.aligned.m8n8.x4.shared.b16 {%0,%1,%2,%3}, [%4];"
                 : "=r"(r0), "=r"(r1), "=r"(r2), "=r"(r3) : "r"(addr));
}
__device__ __forceinline__ void cpasync16(u32 dst, const void* src) {
    asm volatile("cp.async.cg.shared.global [%0], [%1], 16;" :: "r"(dst), "l"(src));
}
__device__ __forceinline__ void cp_commit() { asm volatile("cp.async.commit_group;"); }
__device__ __forceinline__ void cp_wait0()  { asm volatile("cp.async.wait_group 0;"); }
__device__ __forceinline__ void cp_wait1()  { asm volatile("cp.async.wait_group 1;"); }

// Scratch
__device__ float g_G_part[BATCH * NPB * KROWS * CCH];
__device__ float g_s_part[BATCH * NPB * KROWS];
__device__ float g_G[BATCH * KROWS * CCH];
__device__ float g_s[BATCH * KROWS];
__device__ float g_M[BATCH * CCH * CCH];

// cp.async one 64x128 f32 tile into raw buffer (word offset off)
__device__ __forceinline__ void tile_issue(u32 sbase, u32 off, const float* xb,
                                           int s, int tid) {
#pragma unroll
    for (int i = 0; i < 4; ++i) {
        int idx = i * 512 + tid;
        int row = idx >> 5, c16 = idx & 31;
        cpasync16(sbase + (off + (u32)(row * RAWS + c16 * 4)) * 4,
                  xb + (size_t)row * NTOK + (size_t)s * TN + c16 * 4);
    }
}

// stage raw f32 -> X2 hi/lo bf16 planes ([c][n], stride SW2)
__device__ __forceinline__ void tile_stage(const u32* sm, u32* X2h, u32* X2l,
                                           int cur, int wrp, int lane) {
    const float* rp = reinterpret_cast<const float*>(sm) + cur * RAWW;
    const int lc = 4 * wrp;
#pragma unroll
    for (int r = 0; r < 4; ++r) {
        float4 v = *reinterpret_cast<const float4*>(rp + (lc + r) * RAWS + 4 * lane);
        u32 h0 = pk(bhi(v.x), bhi(v.y));
        u32 h1 = pk(bhi(v.z), bhi(v.w));
        u32 l0 = losplit(h0, v.x, v.y);
        u32 l1 = losplit(h1, v.z, v.w);
        *reinterpret_cast<uint2*>(&X2h[(lc + r) * SW2 + 2 * lane]) = make_uint2(h0, h1);
        *reinterpret_cast<uint2*>(&X2l[(lc + r) * SW2 + 2 * lane]) = make_uint2(l0, l1);
    }
}

// ---------------------------------------------------------------------------
// Kernel 1: per 128-col tile: k = Wk*X (bf16x3), p = exp(k) in registers,
// G += P*X^T (bf16x3, P re-used as A-fragments directly).
// 16 warps: (ms 0..7 d-strip) x (nh 0..1 n-half). G halves combined via smem.
// ---------------------------------------------------------------------------
__global__ void __launch_bounds__(512, 1)
kv_ctx_kernel(const float* __restrict__ x, const float* __restrict__ wqkv)
{
    extern __shared__ __align__(16) u32 sm[];
    u32* X2h = sm + X2OFF;
    u32* X2l = sm + X2OFF + 4352;
    float* sred = reinterpret_cast<float*>(sm + SREDOFF);
    u32 sbase;
    asm("{ .reg .u64 t; cvta.to.shared.u64 t, %1; cvt.u32.u64 %0, t; }"
        : "=r"(sbase) : "l"(sm));

    const int tid  = threadIdx.x;
    const int wrp  = tid >> 5;
    const int lane = tid & 31;
    const int g    = lane >> 2;
    const int t    = lane & 3;
    const int ms   = wrp & 7;
    const int nh   = wrp >> 3;

    const int b    = blockIdx.x / NPB;
    const int part = blockIdx.x - b * NPB;
    const int s0   = (part * TILES) / NPB;
    const int s1   = ((part + 1) * TILES) / NPB;

    // Wk fragments (rows 128 + 16*ms .. +16), bf16 hi/lo
    u32 wh[4][4], wl[4][4];
    {
        const float* w0 = wqkv + (size_t)(128 + 16 * ms + g) * 64;
        const float* w1 = w0 + (size_t)8 * 64;
#pragma unroll
        for (int kc = 0; kc < 4; ++kc) {
            sp2(w0[16*kc + 2*t],     w0[16*kc + 2*t + 1], wh[kc][0], wl[kc][0]);
            sp2(w1[16*kc + 2*t],     w1[16*kc + 2*t + 1], wh[kc][1], wl[kc][1]);
            sp2(w0[16*kc + 2*t + 8], w0[16*kc + 2*t + 9], wh[kc][2], wl[kc][2]);
            sp2(w1[16*kc + 2*t + 8], w1[16*kc + 2*t + 9], wh[kc][3], wl[kc][3]);
        }
    }

    float ga[8][4];
#pragma unroll
    for (int cb = 0; cb < 8; ++cb) { ga[cb][0]=ga[cb][1]=ga[cb][2]=ga[cb][3]=0.f; }
    float srow0 = 0.f, srow1 = 0.f;

    // ldmatrix base byte-offsets (lane-dependent)
    const u32 X2hB = sbase + X2OFF * 4;
    const int r1l = lane & 15;                          // GEMM1 (trans): rows = c
    const int w1o = (lane >> 4) << 2;                   // n-word select
    const u32 a1base = X2hB + (u32)((r1l * SW2 + nh * 32 + w1o) * 4);
    const int r2l = ((lane >> 4) & 1) * 8 + (lane & 7); // GEMM2: rows = c
    const int w2o = ((lane >> 3) & 1) * 4;
    const u32 a2base = X2hB + (u32)((r2l * SW2 + nh * 32 + w2o) * 4);

    const float* xb = x + (size_t)b * CCH * NTOK;

    tile_issue(sbase, 0, xb, s0, tid);
    cp_commit();

    for (int s = s0; s < s1; ++s) {
        const int cur = (s - s0) & 1;
        if (s + 1 < s1) {
            tile_issue(sbase, (cur ^ 1) * RAWW, xb, s + 1, tid);
            cp_commit();
            cp_wait1();
        } else {
            cp_wait0();
        }
        __syncthreads();          // raw[cur] ready AND prev compute done
        tile_stage(sm, X2h, X2l, cur, wrp, lane);
        __syncthreads();

#pragma unroll
        for (int p = 0; p < 4; ++p) {
            // ---- GEMM1: C pair (16 d x 16 n) ----
            float C0[4] = {0.f,0.f,0.f,0.f}, C1[4] = {0.f,0.f,0.f,0.f};
#pragma unroll
            for (int kc = 0; kc < 4; ++kc) {
                const u32 ah = a1base + (u32)(kc * (16 * SW2 * 4) + p * 32);
                u32 h0,h1,h2,h3, l0,l1,l2,l3;
                ldsm4t(h0, h1, h2, h3, ah);
                ldsm4t(l0, l1, l2, l3, ah + PLANEB);
                mma16(C0, wh[kc], h0, h1);
                mma16(C0, wh[kc], l0, l1);
                mma16(C0, wl[kc], h0, h1);
                mma16(C1, wh[kc], h2, h3);
                mma16(C1, wh[kc], l2, l3);
                mma16(C1, wl[kc], h2, h3);
            }
            // ---- exp in registers -> P fragments ----
            float e00 = __expf(C0[0]), e01 = __expf(C0[1]);
            float e02 = __expf(C0[2]), e03 = __expf(C0[3]);
            float e10 = __expf(C1[0]), e11 = __expf(C1[1]);
            float e12 = __expf(C1[2]), e13 = __expf(C1[3]);
            srow0 += e00 + e01 + e10 + e11;
            srow1 += e02 + e03 + e12 + e13;
            u32 Ah[4], Al[4];
            Ah[0] = pk(bhi(e00), bhi(e01)); Al[0] = losplit(Ah[0], e00, e01);
            Ah[1] = pk(bhi(e02), bhi(e03)); Al[1] = losplit(Ah[1], e02, e03);
            Ah[2] = pk(bhi(e10), bhi(e11)); Al[2] = losplit(Ah[2], e10, e11);
            Ah[3] = pk(bhi(e12), bhi(e13)); Al[3] = losplit(Ah[3], e12, e13);
            // ---- GEMM2: G += P * X^T over this 16-n k-block ----
#pragma unroll
            for (int pp = 0; pp < 4; ++pp) {
                const u32 a2 = a2base + (u32)(pp * (16 * SW2 * 4) + p * 32);
                u32 h0,h1,h2,h3, l0,l1,l2,l3;
                ldsm4(h0, h1, h2, h3, a2);
                ldsm4(l0, l1, l2, l3, a2 + PLANEB);
                mma16(ga[2*pp],   Ah, h0, h1);
                mma16(ga[2*pp],   Ah, l0, l1);
                mma16(ga[2*pp],   Al, h0, h1);
                mma16(ga[2*pp+1], Ah, h2, h3);
                mma16(ga[2*pp+1], Ah, l2, l3);
                mma16(ga[2*pp+1], Al, h2, h3);
            }
        }
    }

    // ---- s reduce ----
    srow0 += __shfl_xor_sync(0xffffffffu, srow0, 1);
    srow0 += __shfl_xor_sync(0xffffffffu, srow0, 2);
    srow1 += __shfl_xor_sync(0xffffffffu, srow1, 1);
    srow1 += __shfl_xor_sync(0xffffffffu, srow1, 2);
    if (t == 0) {
        sred[nh * 128 + 16 * ms + g]     = srow0;
        sred[nh * 128 + 16 * ms + g + 8] = srow1;
    }
    __syncthreads();

    // ---- combine G halves across nh via smem (reuse raw area) ----
    float* gred = reinterpret_cast<float*>(sm);
    const int r0 = 16 * ms + g, r1 = r0 + 8;
    if (nh == 1) {
#pragma unroll
        for (int cb = 0; cb < 8; ++cb) {
            const int col = cb * 8 + 2 * t;
            *reinterpret_cast<float2*>(&gred[r0 * 64 + col]) = make_float2(ga[cb][0], ga[cb][1]);
            *reinterpret_cast<float2*>(&gred[r1 * 64 + col]) = make_float2(ga[cb][2], ga[cb][3]);
        }
    }
    __syncthreads();
    if (nh == 0) {
        float* gp = g_G_part + (size_t)(b * NPB + part) * (KROWS * CCH);
#pragma unroll
        for (int cb = 0; cb < 8; ++cb) {
            const int col = cb * 8 + 2 * t;
            *reinterpret_cast<float2*>(gp + (size_t)r0 * CCH + col) =
                make_float2(ga[cb][0] + gred[r0 * 64 + col], ga[cb][1] + gred[r0 * 64 + col + 1]);
            *reinterpret_cast<float2*>(gp + (size_t)r1 * CCH + col) =
                make_float2(ga[cb][2] + gred[r1 * 64 + col], ga[cb][3] + gred[r1 * 64 + col + 1]);
        }
    }
    if (tid < KROWS)
        g_s_part[(size_t)(b * NPB + part) * KROWS + tid] = sred[tid] + sred[128 + tid];
}

// ---------------------------------------------------------------------------
// Kernel 2a: reduce partials over NPB parts
// ---------------------------------------------------------------------------
__global__ void __launch_bounds__(256)
reduce_G_kernel()
{
    const int b   = blockIdx.x >> 5;
    const int idx = (blockIdx.x & 31) * 256 + threadIdx.x;
    const float* p = g_G_part + (size_t)b * NPB * (KROWS * CCH) + idx;
    float acc = 0.f;
#pragma unroll 8
    for (int j = 0; j < NPB; ++j) acc += p[(size_t)j * (KROWS * CCH)];
    g_G[(size_t)b * (KROWS * CCH) + idx] = acc;

    if ((blockIdx.x & 31) == 0 && threadIdx.x < KROWS) {
        const float* q = g_s_part + (size_t)b * NPB * KROWS + threadIdx.x;
        float a2 = 0.f;
#pragma unroll 8
        for (int j = 0; j < NPB; ++j) a2 += q[j * KROWS];
        g_s[b * KROWS + threadIdx.x] = a2;
    }
}

// ---------------------------------------------------------------------------
// Kernel 2b: ctx -> T -> M  (tiny, one block per batch)
// ---------------------------------------------------------------------------
__global__ void __launch_bounds__(256)
proj_kernel(const float* __restrict__ wqkv, const float* __restrict__ wout)
{
    const int b   = blockIdx.x;
    const int tid = threadIdx.x;
    __shared__ float ctxn[KROWS * 32];
    __shared__ float Ts[KROWS * CCH];

    const float* Gb = g_G + (size_t)b * (KROWS * CCH);
    const float* sb = g_s + b * KROWS;

    for (int idx = tid; idx < KROWS * 32; idx += 256) {
        const int d = idx >> 5, e = idx & 31, h = d >> 5;
        const float* wv = wqkv + (size_t)(256 + h * 32 + e) * 64;
        const float* gr = Gb + (size_t)d * CCH;
        float acc = 0.f;
#pragma unroll 8
        for (int c = 0; c < CCH; ++c) acc = fmaf(wv[c], gr[c], acc);
        ctxn[idx] = acc / sb[d];
    }
    __syncthreads();

    for (int idx = tid; idx < KROWS * CCH; idx += 256) {
        const int o = idx >> 6, c = idx & 63;
        const int h = o >> 5, e = o & 31;
        float acc = 0.f;
#pragma unroll 8
        for (int dd = 0; dd < 32; ++dd)
            acc = fmaf(ctxn[((h * 32 + dd) << 5) + e], wqkv[(size_t)(h * 32 + dd) * 64 + c], acc);
        Ts[idx] = acc;
    }
    __syncthreads();

    for (int idx = tid; idx < CCH * CCH; idx += 256) {
        const int c1 = idx >> 6, c2 = idx & 63;
        float acc = 0.f;
#pragma unroll 8
        for (int o = 0; o < KROWS; ++o)
            acc = fmaf(wout[(size_t)c1 * KROWS + o], Ts[o * CCH + c2], acc);
        g_M[(size_t)b * (CCH * CCH) + idx] = acc;
    }
}

// ---------------------------------------------------------------------------
// Kernel 3: out = M*X + b_out. 16 warps = (ms 0..3) x (nh 0..3), TN=128,
// cp.async raw + bf16 hi/lo plane, trans-ldmatrix B fragments.
// ---------------------------------------------------------------------------
__global__ void __launch_bounds__(512, 1)
out_proj_kernel(const float* __restrict__ x, const float* __restrict__ bout,
                float* __restrict__ out)
{
    extern __shared__ __align__(16) u32 sm[];
    u32* X2h = sm + X2OFF;
    u32* X2l = sm + X2OFF + 4352;
    u32 sbase;
    asm("{ .reg .u64 t; cvta.to.shared.u64 t, %1; cvt.u32.u64 %0, t; }"
        : "=r"(sbase) : "l"(sm));

    const int tid  = threadIdx.x;
    const int wrp  = tid >> 5;
    const int lane = tid & 31;
    const int g    = lane >> 2;
    const int t    = lane & 3;
    const int ms   = wrp & 3;
    const int nh   = wrp >> 2;

    const int b    = blockIdx.x / NPB;
    const int part = blockIdx.x - b * NPB;
    const int s0   = (part * TILES) / NPB;
    const int s1   = ((part + 1) * TILES) / NPB;

    // M fragments
    u32 mh[4][4], ml[4][4];
    {
        const float* M0 = g_M + (size_t)b * (CCH * CCH) + (size_t)(16 * ms + g) * 64;
        const float* M1 = M0 + (size_t)8 * 64;
#pragma unroll
        for (int kc = 0; kc < 4; ++kc) {
            sp2(M0[16*kc + 2*t],     M0[16*kc + 2*t + 1], mh[kc][0], ml[kc][0]);
            sp2(M1[16*kc + 2*t],     M1[16*kc + 2*t + 1], mh[kc][1], ml[kc][1]);
            sp2(M0[16*kc + 2*t + 8], M0[16*kc + 2*t + 9], mh[kc][2], ml[kc][2]);
            sp2(M1[16*kc + 2*t + 8], M1[16*kc + 2*t + 9], mh[kc][3], ml[kc][3]);
        }
    }
    const float bias0 = bout[16 * ms + g];
    const float bias1 = bout[16 * ms + g + 8];

    const u32 X2hB = sbase + X2OFF * 4;
    const int r1l = lane & 15;
    const int w1o = (lane >> 4) << 2;
    const u32 a1base = X2hB + (u32)((r1l * SW2 + nh * 16 + w1o) * 4);

    const float* xb = x   + (size_t)b * CCH * NTOK;
    float*       ob = out + (size_t)b * CCH * NTOK;

    tile_issue(sbase, 0, xb, s0, tid);
    cp_commit();

    for (int s = s0; s < s1; ++s) {
        const int cur = (s - s0) & 1;
        if (s + 1 < s1) {
            tile_issue(sbase, (cur ^ 1) * RAWW, xb, s + 1, tid);
            cp_commit();
            cp_wait1();
        } else {
            cp_wait0();
        }
        __syncthreads();
        tile_stage(sm, X2h, X2l, cur, wrp, lane);
        __syncthreads();

        float C[4][4];
#pragma unroll
        for (int nb = 0; nb < 4; ++nb) { C[nb][0]=C[nb][1]=C[nb][2]=C[nb][3]=0.f; }
#pragma unroll
        for (int kc = 0; kc < 4; ++kc) {
#pragma unroll
            for (int pp = 0; pp < 2; ++pp) {
                const u32 ah = a1base + (u32)(kc * (16 * SW2 * 4) + pp * 32);
                u32 h0,h1,h2,h3, l0,l1,l2,l3;
                ldsm4t(h0, h1, h2, h3, ah);
                ldsm4t(l0, l1, l2, l3, ah + PLANEB);
                mma16(C[2*pp],   mh[kc], h0, h1);
                mma16(C[2*pp],   mh[kc], l0, l1);
                mma16(C[2*pp],   ml[kc], h0, h1);
                mma16(C[2*pp+1], mh[kc], h2, h3);
                mma16(C[2*pp+1], mh[kc], l2, l3);
                mma16(C[2*pp+1], ml[kc], h2, h3);
            }
        }

        const int r0 = 16 * ms + g, r1 = r0 + 8;
#pragma unroll
        for (int nb = 0; nb < 4; ++nb) {
            const int n = s * TN + nh * 32 + nb * 8 + 2 * t;
            *reinterpret_cast<float2*>(ob + (size_t)r0 * NTOK + n) =
                make_float2(C[nb][0] + bias0, C[nb][1] + bias0);
            *reinterpret_cast<float2*>(ob + (size_t)r1 * NTOK + n) =
                make_float2(C[nb][2] + bias1, C[nb][3] + bias1);
        }
    }
}

extern "C" void kernel_launch(void* const* d_in, const int* in_sizes, int n_in,
                              void* d_out, int out_size)
{
    const float* x    = (const float*)d_in[0];
    const float* wqkv = (const float*)d_in[1];
    const float* wout = (const float*)d_in[2];
    const float* bout = (const float*)d_in[3];
    float* out = (float*)d_out;

    const int smem_k1 = (SREDOFF + 256) * 4;   // 103424 B
    const int smem_k3 = SREDOFF * 4;           // 102400 B
    cudaFuncSetAttribute(kv_ctx_kernel,   cudaFuncAttributeMaxDynamicSharedMemorySize, smem_k1);
    cudaFuncSetAttribute(out_proj_kernel, cudaFuncAttributeMaxDynamicSharedMemorySize, smem_k3);

    kv_ctx_kernel<<<BATCH * NPB, 512, smem_k1>>>(x, wqkv);
    reduce_G_kernel<<<BATCH * 32, 256>>>();
    proj_kernel<<<BATCH, 256>>>(wqkv, wout);
    out_proj_kernel<<<BATCH * NPB, 512, smem_k3>>>(x, bout, out);
}